// round 1
// baseline (speedup 1.0000x reference)
#include <cuda_runtime.h>
#include <math.h>

// ---------------------------------------------------------------------------
// Problem constants
// ---------------------------------------------------------------------------
constexpr int CB  = 4;       // batch
constexpr int CN  = 4096;    // sequence
constexpr int CD  = 512;     // model dim
constexpr int CH  = 8;       // heads
constexpr int CDH = 64;      // dim head
constexpr int CM  = 256;     // landmarks
constexpr int CL  = 16;      // tokens per landmark group
constexpr int CBH = CB * CH; // 32
constexpr int CT3 = 3 * CD;  // 1536
constexpr float EPS = 1e-5f;

// ---------------------------------------------------------------------------
// Device scratch (static __device__ arrays; no allocations anywhere)
// ---------------------------------------------------------------------------
__device__ float g_xn  [(size_t)CB * CN * CD];         // layernormed x
__device__ float g_qkv [(size_t)CB * CN * CT3];        // qkv projection
__device__ float g_q   [(size_t)CBH * CN * CDH];       // (bh, n, dh), pre-scaled
__device__ float g_k   [(size_t)CBH * CN * CDH];
__device__ float g_v   [(size_t)CBH * CN * CDH];
__device__ float g_kT  [(size_t)CBH * CDH * CN];       // (bh, dh, n)
__device__ float g_ql  [(size_t)CBH * CM * CDH];
__device__ float g_klT [(size_t)CBH * CDH * CM];       // (bh, dh, m)
__device__ float g_a1  [(size_t)CBH * CN * CM];        // attn1 (softmaxed in place)
__device__ float g_a3  [(size_t)CBH * CM * CN];        // attn3
__device__ float g_a2  [(size_t)CBH * CM * CM];        // attn2
__device__ float g_z   [(size_t)CBH * CM * CM];
__device__ float g_z2  [(size_t)CBH * CM * CM];
__device__ float g_xz  [(size_t)CBH * CM * CM];
__device__ float g_t   [(size_t)CBH * CM * CM];
__device__ float g_u   [(size_t)CBH * CM * CM];
__device__ float g_av  [(size_t)CBH * CM * CDH];       // attn3 @ v
__device__ float g_zav [(size_t)CBH * CM * CDH];       // z @ av
__device__ float g_outh[(size_t)CBH * CN * CDH];       // attn1 @ zav (+conv res)
__device__ unsigned g_maxc, g_maxr;                    // pinv init scale (f32 bits)

// ---------------------------------------------------------------------------
// LayerNorm: one block (128 threads) per row of 512
// ---------------------------------------------------------------------------
__global__ void ln_kernel(const float* __restrict__ x,
                          const float* __restrict__ gamma,
                          const float* __restrict__ beta) {
    int row = blockIdx.x;
    int t = threadIdx.x;  // 128
    const float4* xr = (const float4*)(x + (size_t)row * CD);
    float4 v = xr[t];
    float s  = v.x + v.y + v.z + v.w;
    float ss = v.x * v.x + v.y * v.y + v.z * v.z + v.w * v.w;
    __shared__ float shs[4], shss[4];
#pragma unroll
    for (int o = 16; o > 0; o >>= 1) {
        s  += __shfl_down_sync(0xffffffffu, s,  o);
        ss += __shfl_down_sync(0xffffffffu, ss, o);
    }
    int wid = t >> 5, lane = t & 31;
    if (!lane) { shs[wid] = s; shss[wid] = ss; }
    __syncthreads();
    s  = shs[0]  + shs[1]  + shs[2]  + shs[3];
    ss = shss[0] + shss[1] + shss[2] + shss[3];
    float mean = s * (1.0f / CD);
    float var  = ss * (1.0f / CD) - mean * mean;
    float inv  = rsqrtf(var + EPS);
    float4 gg = ((const float4*)gamma)[t];
    float4 bb = ((const float4*)beta)[t];
    float4 o;
    o.x = (v.x - mean) * inv * gg.x + bb.x;
    o.y = (v.y - mean) * inv * gg.y + bb.y;
    o.z = (v.z - mean) * inv * gg.z + bb.z;
    o.w = (v.w - mean) * inv * gg.w + bb.w;
    ((float4*)(g_xn + (size_t)row * CD))[t] = o;
}

// ---------------------------------------------------------------------------
// Generic batched SGEMM (NN): C = alpha * A @ (diagc*I + bsign*B)
// 64x64 tile, 256 threads, 4x4 micro-tile, K-step 16.
// All M, Ncols multiples of 64; K multiple of 16. Grid: (Ncols/64, M/64, batch)
// ---------------------------------------------------------------------------
__global__ __launch_bounds__(256)
void sgemm_nn(const float* __restrict__ A, const float* __restrict__ Bm,
              float* __restrict__ C,
              int K, int lda, int ldb, int ldc,
              size_t sA, size_t sB, size_t sC,
              float alpha, float diagc, float bsign) {
    __shared__ float As[16][65];
    __shared__ float Bs[16][64];
    const float* Ab = A + (size_t)blockIdx.z * sA;
    const float* Bb = Bm + (size_t)blockIdx.z * sB;
    float* Cb = C + (size_t)blockIdx.z * sC;
    int rowBase = blockIdx.y * 64, colBase = blockIdx.x * 64;
    int t = threadIdx.x;
    int tx = t & 15, ty = t >> 4;
    float acc[4][4] = {};
    for (int k0 = 0; k0 < K; k0 += 16) {
#pragma unroll
        for (int i = 0; i < 4; i++) {
            int li = t + i * 256;
            int r = li >> 4, kk = li & 15;
            As[kk][r] = Ab[(size_t)(rowBase + r) * lda + k0 + kk];
        }
#pragma unroll
        for (int i = 0; i < 4; i++) {
            int li = t + i * 256;
            int r = li >> 6, c = li & 63;
            float bv = Bb[(size_t)(k0 + r) * ldb + colBase + c];
            bv = bsign * bv + ((k0 + r) == (colBase + c) ? diagc : 0.0f);
            Bs[r][c] = bv;
        }
        __syncthreads();
#pragma unroll
        for (int kk = 0; kk < 16; kk++) {
            float a0 = As[kk][ty * 4 + 0];
            float a1 = As[kk][ty * 4 + 1];
            float a2 = As[kk][ty * 4 + 2];
            float a3 = As[kk][ty * 4 + 3];
            float4 bv = *(const float4*)&Bs[kk][tx * 4];
            acc[0][0] += a0 * bv.x; acc[0][1] += a0 * bv.y; acc[0][2] += a0 * bv.z; acc[0][3] += a0 * bv.w;
            acc[1][0] += a1 * bv.x; acc[1][1] += a1 * bv.y; acc[1][2] += a1 * bv.z; acc[1][3] += a1 * bv.w;
            acc[2][0] += a2 * bv.x; acc[2][1] += a2 * bv.y; acc[2][2] += a2 * bv.z; acc[2][3] += a2 * bv.w;
            acc[3][0] += a3 * bv.x; acc[3][1] += a3 * bv.y; acc[3][2] += a3 * bv.z; acc[3][3] += a3 * bv.w;
        }
        __syncthreads();
    }
#pragma unroll
    for (int i = 0; i < 4; i++) {
        float4 o = make_float4(alpha * acc[i][0], alpha * acc[i][1],
                               alpha * acc[i][2], alpha * acc[i][3]);
        *(float4*)&Cb[(size_t)(rowBase + ty * 4 + i) * ldc + colBase + tx * 4] = o;
    }
}

// ---------------------------------------------------------------------------
// Split qkv -> q (scaled 1/8), k, kT, v
// ---------------------------------------------------------------------------
__global__ void scatter_qkv() {
    int idx = blockIdx.x * 256 + threadIdx.x;  // B*N*1536 elems
    int c  = idx % CT3;
    int bn = idx / CT3;
    int n  = bn & (CN - 1);
    int b_ = bn >> 12;
    float val = g_qkv[(size_t)idx];
    int which = c >> 9;
    int inner = c & 511;
    int h_ = inner >> 6;
    int dh = inner & 63;
    size_t o = (((size_t)(b_ * CH + h_)) * CN + n) * CDH + dh;
    if (which == 0) {
        g_q[o] = val * 0.125f;  // Dh^-0.5
    } else if (which == 1) {
        g_k[o] = val;
        g_kT[(((size_t)(b_ * CH + h_)) * CDH + dh) * CN + n] = val;
    } else {
        g_v[o] = val;
    }
}

// ---------------------------------------------------------------------------
// Landmark means: q_l (bh,m,dh) and k_l transposed (bh,dh,m)
// ---------------------------------------------------------------------------
__global__ void landmark_kernel() {
    int idx = blockIdx.x * 256 + threadIdx.x;  // BH*M*DH = 524288
    int dh = idx & 63;
    int mi = (idx >> 6) & 255;
    int bh = idx >> 14;
    size_t base = ((size_t)bh * CN + mi * CL) * CDH + dh;
    float sq = 0.0f, sk = 0.0f;
#pragma unroll
    for (int j = 0; j < CL; j++) {
        sq += g_q[base + (size_t)j * CDH];
        sk += g_k[base + (size_t)j * CDH];
    }
    g_ql [((size_t)bh * CM + mi) * CDH + dh] = sq * (1.0f / CL);
    g_klT[((size_t)bh * CDH + dh) * CM + mi] = sk * (1.0f / CL);
}

// ---------------------------------------------------------------------------
// Row softmax (in place). IT = elements per thread (len = 256*IT). 256 threads.
// ---------------------------------------------------------------------------
template <int IT>
__global__ void softmax_rows(float* __restrict__ p, int len) {
    float* r = p + (size_t)blockIdx.x * len;
    int t = threadIdx.x;
    float vals[IT];
    float mx = -3.4e38f;
#pragma unroll
    for (int i = 0; i < IT; i++) {
        vals[i] = r[t + i * 256];
        mx = fmaxf(mx, vals[i]);
    }
    __shared__ float sh[8];
#pragma unroll
    for (int o = 16; o > 0; o >>= 1) mx = fmaxf(mx, __shfl_xor_sync(0xffffffffu, mx, o));
    int wid = t >> 5, lane = t & 31;
    if (!lane) sh[wid] = mx;
    __syncthreads();
    mx = sh[0];
#pragma unroll
    for (int w = 1; w < 8; w++) mx = fmaxf(mx, sh[w]);
    __syncthreads();
    float s = 0.0f;
#pragma unroll
    for (int i = 0; i < IT; i++) {
        vals[i] = expf(vals[i] - mx);
        s += vals[i];
    }
#pragma unroll
    for (int o = 16; o > 0; o >>= 1) s += __shfl_xor_sync(0xffffffffu, s, o);
    if (!lane) sh[wid] = s;
    __syncthreads();
    s = sh[0];
#pragma unroll
    for (int w = 1; w < 8; w++) s += sh[w];
    float inv = 1.0f / s;
#pragma unroll
    for (int i = 0; i < IT; i++) r[t + i * 256] = vals[i] * inv;
}

// ---------------------------------------------------------------------------
// Pinv init scale: global max of row-sums and col-sums of |attn2|
// ---------------------------------------------------------------------------
__global__ void init_scalars() { g_maxc = 0u; g_maxr = 0u; }

__global__ void absmax_sums() {
    int bh = blockIdx.x;
    int t = threadIdx.x;  // 256
    const float* a = g_a2 + (size_t)bh * CM * CM;
    float rs = 0.0f, cs = 0.0f;
    for (int j = 0; j < CM; j++) rs += fabsf(a[(size_t)t * CM + j]);
    for (int i = 0; i < CM; i++) cs += fabsf(a[(size_t)i * CM + t]);
    atomicMax(&g_maxc, __float_as_uint(rs));  // abs.sum(-1) max
    atomicMax(&g_maxr, __float_as_uint(cs));  // abs.sum(-2) max
}

__global__ void zinit_kernel() {
    int idx = blockIdx.x * 256 + threadIdx.x;  // BH*M*M
    int j = idx & 255;
    int i = (idx >> 8) & 255;
    int bh = idx >> 16;
    float denom = __uint_as_float(g_maxc) * __uint_as_float(g_maxr);
    g_z[((size_t)bh << 16) + (size_t)i * CM + j] =
        g_a2[((size_t)bh << 16) + (size_t)j * CM + i] / denom;
}

// ---------------------------------------------------------------------------
// Depthwise conv residual over sequence dim, added into g_outh
// ---------------------------------------------------------------------------
__global__ void conv_res(const float* __restrict__ w) {
    int idx = blockIdx.x * 256 + threadIdx.x;  // BH*N*DH = 8388608
    int dh = idx & 63;
    int n  = (idx >> 6) & (CN - 1);
    int bh = idx >> 18;
    int h_ = bh & 7;
    size_t base = ((size_t)bh * CN) * CDH + dh;
    float s = 0.0f;
#pragma unroll
    for (int k = 0; k < 33; k++) {
        int nn = n + k - 16;
        if (nn >= 0 && nn < CN) s += w[h_ * 33 + k] * g_v[base + (size_t)nn * CDH];
    }
    g_outh[(size_t)idx] += s;
}

// ---------------------------------------------------------------------------
// Final GEMM: out[b,n,:] = x + (head-permuted outh) @ W_out + b_out
// rows = B*N = 16384, cols = 512, K = 512. Gathered A-side.
// ---------------------------------------------------------------------------
__global__ __launch_bounds__(256)
void final_gemm(const float* __restrict__ x, const float* __restrict__ Wout,
                const float* __restrict__ bout, float* __restrict__ out) {
    __shared__ float As[16][65];
    __shared__ float Bs[16][64];
    int rowBase = blockIdx.y * 64, colBase = blockIdx.x * 64;
    int t = threadIdx.x;
    int tx = t & 15, ty = t >> 4;
    float acc[4][4] = {};
    for (int k0 = 0; k0 < CD; k0 += 16) {
#pragma unroll
        for (int i = 0; i < 4; i++) {
            int li = t + i * 256;
            int r = li >> 4, kk = li & 15;
            int row = rowBase + r;
            int c = k0 + kk;
            int b_ = row >> 12, n = row & (CN - 1);
            int h_ = c >> 6, dh = c & 63;
            As[kk][r] = g_outh[((((size_t)b_ << 3) + h_) * CN + n) * CDH + dh];
        }
#pragma unroll
        for (int i = 0; i < 4; i++) {
            int li = t + i * 256;
            int r = li >> 6, c = li & 63;
            Bs[r][c] = Wout[(size_t)(k0 + r) * CD + colBase + c];
        }
        __syncthreads();
#pragma unroll
        for (int kk = 0; kk < 16; kk++) {
            float a0 = As[kk][ty * 4 + 0];
            float a1 = As[kk][ty * 4 + 1];
            float a2 = As[kk][ty * 4 + 2];
            float a3 = As[kk][ty * 4 + 3];
            float4 bv = *(const float4*)&Bs[kk][tx * 4];
            acc[0][0] += a0 * bv.x; acc[0][1] += a0 * bv.y; acc[0][2] += a0 * bv.z; acc[0][3] += a0 * bv.w;
            acc[1][0] += a1 * bv.x; acc[1][1] += a1 * bv.y; acc[1][2] += a1 * bv.z; acc[1][3] += a1 * bv.w;
            acc[2][0] += a2 * bv.x; acc[2][1] += a2 * bv.y; acc[2][2] += a2 * bv.z; acc[2][3] += a2 * bv.w;
            acc[3][0] += a3 * bv.x; acc[3][1] += a3 * bv.y; acc[3][2] += a3 * bv.z; acc[3][3] += a3 * bv.w;
        }
        __syncthreads();
    }
    float4 bo = *(const float4*)&bout[colBase + tx * 4];
#pragma unroll
    for (int i = 0; i < 4; i++) {
        int row = rowBase + ty * 4 + i;
        float4 xo = *(const float4*)&x[(size_t)row * CD + colBase + tx * 4];
        float4 o;
        o.x = acc[i][0] + xo.x + bo.x;
        o.y = acc[i][1] + xo.y + bo.y;
        o.z = acc[i][2] + xo.z + bo.z;
        o.w = acc[i][3] + xo.w + bo.w;
        *(float4*)&out[(size_t)row * CD + colBase + tx * 4] = o;
    }
}

// ---------------------------------------------------------------------------
// Launch
// ---------------------------------------------------------------------------
extern "C" void kernel_launch(void* const* d_in, const int* in_sizes, int n_in,
                              void* d_out, int out_size) {
    const float* x     = (const float*)d_in[0];
    const float* gamma = (const float*)d_in[1];
    const float* beta  = (const float*)d_in[2];
    const float* Wqkv  = (const float*)d_in[3];
    const float* Wout  = (const float*)d_in[4];
    const float* bout  = (const float*)d_in[5];
    const float* convw = (const float*)d_in[6];
    float* out = (float*)d_out;

    float *xn, *qkv, *q, *k, *v, *kT, *ql, *klT, *a1, *a3, *a2;
    float *z, *z2, *xz, *tb, *ub, *av, *zav, *outh;
    void* p;
    cudaGetSymbolAddress(&p, g_xn);   xn   = (float*)p;
    cudaGetSymbolAddress(&p, g_qkv);  qkv  = (float*)p;
    cudaGetSymbolAddress(&p, g_q);    q    = (float*)p;
    cudaGetSymbolAddress(&p, g_k);    k    = (float*)p;
    cudaGetSymbolAddress(&p, g_v);    v    = (float*)p;
    cudaGetSymbolAddress(&p, g_kT);   kT   = (float*)p;
    cudaGetSymbolAddress(&p, g_ql);   ql   = (float*)p;
    cudaGetSymbolAddress(&p, g_klT);  klT  = (float*)p;
    cudaGetSymbolAddress(&p, g_a1);   a1   = (float*)p;
    cudaGetSymbolAddress(&p, g_a3);   a3   = (float*)p;
    cudaGetSymbolAddress(&p, g_a2);   a2   = (float*)p;
    cudaGetSymbolAddress(&p, g_z);    z    = (float*)p;
    cudaGetSymbolAddress(&p, g_z2);   z2   = (float*)p;
    cudaGetSymbolAddress(&p, g_xz);   xz   = (float*)p;
    cudaGetSymbolAddress(&p, g_t);    tb   = (float*)p;
    cudaGetSymbolAddress(&p, g_u);    ub   = (float*)p;
    cudaGetSymbolAddress(&p, g_av);   av   = (float*)p;
    cudaGetSymbolAddress(&p, g_zav);  zav  = (float*)p;
    cudaGetSymbolAddress(&p, g_outh); outh = (float*)p;

    const size_t MM = (size_t)CM * CM;

    // 1) LayerNorm
    ln_kernel<<<CB * CN, 128>>>(x, gamma, beta);

    // 2) QKV projection: (16384 x 512) @ (512 x 1536)
    sgemm_nn<<<dim3(CT3 / 64, CB * CN / 64, 1), 256>>>(
        xn, Wqkv, qkv, CD, CD, CT3, CT3, 0, 0, 0, 1.0f, 0.0f, 1.0f);

    // 3) Split heads (+ q scale, kT)
    scatter_qkv<<<(CB * CN * CT3) / 256, 256>>>();

    // 4) Landmarks
    landmark_kernel<<<(CBH * CM * CDH) / 256, 256>>>();

    // 5) Similarities (K = 64)
    sgemm_nn<<<dim3(CM / 64, CN / 64, CBH), 256>>>(
        q, klT, a1, CDH, CDH, CM, CM,
        (size_t)CN * CDH, (size_t)CDH * CM, (size_t)CN * CM, 1.0f, 0.0f, 1.0f);
    sgemm_nn<<<dim3(CM / 64, CM / 64, CBH), 256>>>(
        ql, klT, a2, CDH, CDH, CM, CM,
        (size_t)CM * CDH, (size_t)CDH * CM, MM, 1.0f, 0.0f, 1.0f);
    sgemm_nn<<<dim3(CN / 64, CM / 64, CBH), 256>>>(
        ql, kT, a3, CDH, CDH, CN, CN,
        (size_t)CM * CDH, (size_t)CDH * CN, (size_t)CM * CN, 1.0f, 0.0f, 1.0f);

    // 6) Softmaxes
    softmax_rows<1><<<CBH * CN, 256>>>(a1, CM);
    softmax_rows<1><<<CBH * CM, 256>>>(a2, CM);
    softmax_rows<16><<<CBH * CM, 256>>>(a3, CN);

    // 7) Moore-Penrose pinv of attn2 (6 Newton iterations)
    init_scalars<<<1, 1>>>();
    absmax_sums<<<CBH, 256>>>();
    zinit_kernel<<<(CBH * CM * CM) / 256, 256>>>();
    float* zc = z;
    float* zn = z2;
    for (int it = 0; it < 6; it++) {
        // xz = a2 @ z
        sgemm_nn<<<dim3(4, 4, CBH), 256>>>(a2, zc, xz, CM, CM, CM, CM,
                                           MM, MM, MM, 1.0f, 0.0f, 1.0f);
        // t = xz @ (7I - xz)
        sgemm_nn<<<dim3(4, 4, CBH), 256>>>(xz, xz, tb, CM, CM, CM, CM,
                                           MM, MM, MM, 1.0f, 7.0f, -1.0f);
        // u = xz @ (15I - t)
        sgemm_nn<<<dim3(4, 4, CBH), 256>>>(xz, tb, ub, CM, CM, CM, CM,
                                           MM, MM, MM, 1.0f, 15.0f, -1.0f);
        // z_new = 0.25 * z @ (13I - u)
        sgemm_nn<<<dim3(4, 4, CBH), 256>>>(zc, ub, zn, CM, CM, CM, CM,
                                           MM, MM, MM, 0.25f, 13.0f, -1.0f);
        float* tmp = zc; zc = zn; zn = tmp;
    }
    // zc holds the final pseudo-inverse

    // 8) av = attn3 @ v  (256 x 64, K = 4096)
    sgemm_nn<<<dim3(1, CM / 64, CBH), 256>>>(
        a3, v, av, CN, CN, CDH, CDH,
        (size_t)CM * CN, (size_t)CN * CDH, (size_t)CM * CDH, 1.0f, 0.0f, 1.0f);

    // 9) zav = z @ av (256 x 64, K = 256)
    sgemm_nn<<<dim3(1, CM / 64, CBH), 256>>>(
        zc, av, zav, CM, CM, CDH, CDH,
        MM, (size_t)CM * CDH, (size_t)CM * CDH, 1.0f, 0.0f, 1.0f);

    // 10) outh = attn1 @ zav (4096 x 64, K = 256)
    sgemm_nn<<<dim3(1, CN / 64, CBH), 256>>>(
        a1, zav, outh, CM, CM, CDH, CDH,
        (size_t)CN * CM, (size_t)CM * CDH, (size_t)CN * CDH, 1.0f, 0.0f, 1.0f);

    // 11) depthwise conv residual on v, added to outh
    conv_res<<<(CBH * CN * CDH) / 256, 256>>>(convw);

    // 12) final projection + bias + residual x
    final_gemm<<<dim3(CD / 64, CB * CN / 64), 256>>>(x, Wout, bout, out);
}

// round 2
// speedup vs baseline: 1.8455x; 1.8455x over previous
#include <cuda_runtime.h>
#include <math.h>
#include <stdint.h>

// ---------------------------------------------------------------------------
// Problem constants
// ---------------------------------------------------------------------------
constexpr int CB  = 4;
constexpr int CN  = 4096;
constexpr int CD  = 512;
constexpr int CH  = 8;
constexpr int CDH = 64;
constexpr int CM  = 256;
constexpr int CL  = 16;
constexpr int CBH = CB * CH;    // 32
constexpr int CT3 = 3 * CD;     // 1536
constexpr float EPS = 1e-5f;

// ---------------------------------------------------------------------------
// Device scratch
// ---------------------------------------------------------------------------
__device__ float g_xn  [(size_t)CB * CN * CD];
__device__ float g_q   [(size_t)CBH * CN * CDH];
__device__ float g_k   [(size_t)CBH * CN * CDH];
__device__ float g_v   [(size_t)CBH * CN * CDH];
__device__ float g_kT  [(size_t)CBH * CDH * CN];
__device__ float g_ql  [(size_t)CBH * CM * CDH];
__device__ float g_klT [(size_t)CBH * CDH * CM];
__device__ float g_a1  [(size_t)CBH * CN * CM];
__device__ float g_a3  [(size_t)CBH * CM * CN];
__device__ float g_a2  [(size_t)CBH * CM * CM];
__device__ float g_z   [(size_t)CBH * CM * CM];
__device__ float g_z2  [(size_t)CBH * CM * CM];
__device__ float g_xz  [(size_t)CBH * CM * CM];
__device__ float g_t   [(size_t)CBH * CM * CM];
__device__ float g_u   [(size_t)CBH * CM * CM];
__device__ float g_av  [(size_t)CBH * CM * CDH];
__device__ float g_zav [(size_t)CBH * CM * CDH];
__device__ float g_outh[(size_t)CBH * CN * CDH];
__device__ unsigned g_maxc, g_maxr;

// ---------------------------------------------------------------------------
// tf32 helpers
// ---------------------------------------------------------------------------
__device__ __forceinline__ float to_tf32(float x) {
    float y;
    asm("cvt.rna.tf32.f32 %0, %1;" : "=f"(y) : "f"(x));
    return y;
}
__device__ __forceinline__ float4 tf4(float4 v) {
    v.x = to_tf32(v.x); v.y = to_tf32(v.y);
    v.z = to_tf32(v.z); v.w = to_tf32(v.w);
    return v;
}
__device__ __forceinline__ void mma8(float* c, const uint32_t* a,
                                     uint32_t b0, uint32_t b1) {
    asm volatile(
        "mma.sync.aligned.m16n8k8.row.col.f32.tf32.tf32.f32 "
        "{%0,%1,%2,%3},{%4,%5,%6,%7},{%8,%9},{%0,%1,%2,%3};"
        : "+f"(c[0]), "+f"(c[1]), "+f"(c[2]), "+f"(c[3])
        : "r"(a[0]), "r"(a[1]), "r"(a[2]), "r"(a[3]), "r"(b0), "r"(b1));
}

// ---------------------------------------------------------------------------
// Tensor-core tf32 batched GEMM.
//   C = alpha * A @ (diagc*I + bsign*B)
// BM=128, BK=16, 256 threads (8 warps in 4x2), warp tile 32 x (BN/2).
// MODE 0: plain store   MODE 1: QKV scatter epilogue   MODE 2: final (gather A,
//         out = acc + X + bias)
// ---------------------------------------------------------------------------
template <int BN, int MODE>
__global__ __launch_bounds__(256)
void tc_gemm(const float* __restrict__ A, const float* __restrict__ B,
             float* __restrict__ C,
             int K, int lda, int ldb, int ldc,
             size_t sA, size_t sB, size_t sC,
             float alpha, float diagc, float bsign,
             const float* __restrict__ X, const float* __restrict__ bias) {
    constexpr int BM = 128, BK = 16;
    constexpr int WN  = BN / 2;   // warp tile cols
    constexpr int NFR = WN / 8;   // n-fragments per warp
    __shared__ float As[BM][BK + 4];
    __shared__ float Bs[BK][BN + 8];

    const float* Ab = A + (size_t)blockIdx.z * sA;
    const float* Bb = B + (size_t)blockIdx.z * sB;
    float* Cb = C + (size_t)blockIdx.z * sC;
    const int rowBase = blockIdx.y * BM;
    const int colBase = blockIdx.x * BN;
    const int t = threadIdx.x, warp = t >> 5, lane = t & 31;
    const int wm = warp >> 1, wn = warp & 1;
    const int g = lane >> 2, tg = lane & 3;

    // A staging: thread -> (row, 8-wide k chunk)
    const int arow = t & 127, akg = (t >> 7) * 8;
    // B staging
    constexpr int TPR = BN / 4;        // threads per B row
    constexpr int RPP = 256 / TPR;     // rows per pass
    constexpr int BPASS = BK / RPP;    // passes (2 for BN=128, 1 for BN=64)
    const int bcol = (t % TPR) * 4, bk0 = t / TPR;

    float4 pa[2], pb[BPASS];

    auto ldA = [&](int k0) {
        if (MODE == 2) {
            int r = rowBase + arow;
            int b_ = r >> 12, n = r & (CN - 1);
            int c = k0 + akg;
            int h_ = c >> 6, dh = c & 63;
            const float* p = A + ((((size_t)(b_ * CH + h_)) * CN + n) * CDH + dh);
            pa[0] = *(const float4*)p;
            pa[1] = *(const float4*)(p + 4);
        } else {
            const float* p = Ab + (size_t)(rowBase + arow) * lda + k0 + akg;
            pa[0] = *(const float4*)p;
            pa[1] = *(const float4*)(p + 4);
        }
    };
    auto ldB = [&](int k0) {
#pragma unroll
        for (int i = 0; i < BPASS; i++)
            pb[i] = *(const float4*)(Bb + (size_t)(k0 + bk0 + i * RPP) * ldb +
                                     colBase + bcol);
    };
    auto stage = [&](int k0) {
        *(float4*)&As[arow][akg]     = tf4(pa[0]);
        *(float4*)&As[arow][akg + 4] = tf4(pa[1]);
#pragma unroll
        for (int i = 0; i < BPASS; i++) {
            float4 v = pb[i];
            int kr = k0 + bk0 + i * RPP;
            int cb = colBase + bcol;
            v.x = bsign * v.x + ((kr == cb + 0) ? diagc : 0.0f);
            v.y = bsign * v.y + ((kr == cb + 1) ? diagc : 0.0f);
            v.z = bsign * v.z + ((kr == cb + 2) ? diagc : 0.0f);
            v.w = bsign * v.w + ((kr == cb + 3) ? diagc : 0.0f);
            *(float4*)&Bs[bk0 + i * RPP][bcol] = tf4(v);
        }
    };

    float acc[2][NFR][4] = {};

    ldA(0); ldB(0); stage(0);
    __syncthreads();
    for (int k0 = 0;; k0 += BK) {
        const int kn = k0 + BK;
        const bool more = kn < K;
        if (more) { ldA(kn); ldB(kn); }
#pragma unroll
        for (int kk = 0; kk < BK; kk += 8) {
            uint32_t af[2][4];
#pragma unroll
            for (int mi = 0; mi < 2; mi++) {
                int r = wm * 32 + mi * 16 + g;
                af[mi][0] = __float_as_uint(As[r][kk + tg]);
                af[mi][1] = __float_as_uint(As[r + 8][kk + tg]);
                af[mi][2] = __float_as_uint(As[r][kk + tg + 4]);
                af[mi][3] = __float_as_uint(As[r + 8][kk + tg + 4]);
            }
#pragma unroll
            for (int ni = 0; ni < NFR; ni++) {
                uint32_t b0 = __float_as_uint(Bs[kk + tg][wn * WN + ni * 8 + g]);
                uint32_t b1 = __float_as_uint(Bs[kk + tg + 4][wn * WN + ni * 8 + g]);
                mma8(acc[0][ni], af[0], b0, b1);
                mma8(acc[1][ni], af[1], b0, b1);
            }
        }
        if (!more) break;
        __syncthreads();
        stage(kn);
        __syncthreads();
    }

    // epilogue
#pragma unroll
    for (int mi = 0; mi < 2; mi++)
#pragma unroll
        for (int ni = 0; ni < NFR; ni++) {
            int r0 = rowBase + wm * 32 + mi * 16 + g;
            int c0 = colBase + wn * WN + ni * 8 + 2 * tg;
#pragma unroll
            for (int h2 = 0; h2 < 2; h2++) {
                int r = r0 + h2 * 8;
                float vx = alpha * acc[mi][ni][h2 * 2];
                float vy = alpha * acc[mi][ni][h2 * 2 + 1];
                if (MODE == 0) {
                    *(float2*)&Cb[(size_t)r * ldc + c0] = make_float2(vx, vy);
                } else if (MODE == 1) {
                    int b_ = r >> 12, n = r & (CN - 1);
                    int which = c0 >> 9, inner = c0 & 511;
                    int h_ = inner >> 6, dh = inner & 63;
                    size_t off = (((size_t)(b_ * CH + h_)) * CN + n) * CDH + dh;
                    if (which == 0) {
                        *(float2*)&g_q[off] = make_float2(vx * 0.125f, vy * 0.125f);
                    } else if (which == 1) {
                        *(float2*)&g_k[off] = make_float2(vx, vy);
                        size_t ot = (((size_t)(b_ * CH + h_)) * CDH + dh) * CN + n;
                        g_kT[ot]      = vx;
                        g_kT[ot + CN] = vy;
                    } else {
                        *(float2*)&g_v[off] = make_float2(vx, vy);
                    }
                } else {
                    size_t o = (size_t)r * CD + c0;
                    float2 xr = *(const float2*)&X[o];
                    float2 br = *(const float2*)&bias[c0];
                    *(float2*)&Cb[o] = make_float2(vx + xr.x + br.x,
                                                   vy + xr.y + br.y);
                }
            }
        }
}

// ---------------------------------------------------------------------------
// LayerNorm
// ---------------------------------------------------------------------------
__global__ void ln_kernel(const float* __restrict__ x,
                          const float* __restrict__ gamma,
                          const float* __restrict__ beta) {
    int row = blockIdx.x;
    int t = threadIdx.x;
    const float4* xr = (const float4*)(x + (size_t)row * CD);
    float4 v = xr[t];
    float s  = v.x + v.y + v.z + v.w;
    float ss = v.x * v.x + v.y * v.y + v.z * v.z + v.w * v.w;
    __shared__ float shs[4], shss[4];
#pragma unroll
    for (int o = 16; o > 0; o >>= 1) {
        s  += __shfl_down_sync(0xffffffffu, s,  o);
        ss += __shfl_down_sync(0xffffffffu, ss, o);
    }
    int wid = t >> 5, lane = t & 31;
    if (!lane) { shs[wid] = s; shss[wid] = ss; }
    __syncthreads();
    s  = shs[0]  + shs[1]  + shs[2]  + shs[3];
    ss = shss[0] + shss[1] + shss[2] + shss[3];
    float mean = s * (1.0f / CD);
    float var  = ss * (1.0f / CD) - mean * mean;
    float inv  = rsqrtf(var + EPS);
    float4 gg = ((const float4*)gamma)[t];
    float4 bb = ((const float4*)beta)[t];
    float4 o;
    o.x = (v.x - mean) * inv * gg.x + bb.x;
    o.y = (v.y - mean) * inv * gg.y + bb.y;
    o.z = (v.z - mean) * inv * gg.z + bb.z;
    o.w = (v.w - mean) * inv * gg.w + bb.w;
    ((float4*)(g_xn + (size_t)row * CD))[t] = o;
}

// ---------------------------------------------------------------------------
// Landmark means
// ---------------------------------------------------------------------------
__global__ void landmark_kernel() {
    int idx = blockIdx.x * 256 + threadIdx.x;
    int dh = idx & 63;
    int mi = (idx >> 6) & 255;
    int bh = idx >> 14;
    size_t base = ((size_t)bh * CN + mi * CL) * CDH + dh;
    float sq = 0.0f, sk = 0.0f;
#pragma unroll
    for (int j = 0; j < CL; j++) {
        sq += g_q[base + (size_t)j * CDH];
        sk += g_k[base + (size_t)j * CDH];
    }
    g_ql [((size_t)bh * CM + mi) * CDH + dh] = sq * (1.0f / CL);
    g_klT[((size_t)bh * CDH + dh) * CM + mi] = sk * (1.0f / CL);
}

// ---------------------------------------------------------------------------
// Row softmax
// ---------------------------------------------------------------------------
template <int IT>
__global__ void softmax_rows(float* __restrict__ p, int len) {
    float* r = p + (size_t)blockIdx.x * len;
    int t = threadIdx.x;
    float vals[IT];
    float mx = -3.4e38f;
#pragma unroll
    for (int i = 0; i < IT; i++) {
        vals[i] = r[t + i * 256];
        mx = fmaxf(mx, vals[i]);
    }
    __shared__ float sh[8];
#pragma unroll
    for (int o = 16; o > 0; o >>= 1) mx = fmaxf(mx, __shfl_xor_sync(0xffffffffu, mx, o));
    int wid = t >> 5, lane = t & 31;
    if (!lane) sh[wid] = mx;
    __syncthreads();
    mx = sh[0];
#pragma unroll
    for (int w = 1; w < 8; w++) mx = fmaxf(mx, sh[w]);
    __syncthreads();
    float s = 0.0f;
#pragma unroll
    for (int i = 0; i < IT; i++) {
        vals[i] = expf(vals[i] - mx);
        s += vals[i];
    }
#pragma unroll
    for (int o = 16; o > 0; o >>= 1) s += __shfl_xor_sync(0xffffffffu, s, o);
    if (!lane) sh[wid] = s;
    __syncthreads();
    s = sh[0];
#pragma unroll
    for (int w = 1; w < 8; w++) s += sh[w];
    float inv = 1.0f / s;
#pragma unroll
    for (int i = 0; i < IT; i++) r[t + i * 256] = vals[i] * inv;
}

// ---------------------------------------------------------------------------
// Pinv init
// ---------------------------------------------------------------------------
__global__ void init_scalars() { g_maxc = 0u; g_maxr = 0u; }

__global__ void absmax_sums() {
    int bh = blockIdx.x;
    int t = threadIdx.x;
    const float* a = g_a2 + (size_t)bh * CM * CM;
    float rs = 0.0f, cs = 0.0f;
    for (int j = 0; j < CM; j++) rs += fabsf(a[(size_t)t * CM + j]);
    for (int i = 0; i < CM; i++) cs += fabsf(a[(size_t)i * CM + t]);
    atomicMax(&g_maxc, __float_as_uint(rs));
    atomicMax(&g_maxr, __float_as_uint(cs));
}

__global__ void zinit_kernel() {
    int idx = blockIdx.x * 256 + threadIdx.x;
    int j = idx & 255;
    int i = (idx >> 8) & 255;
    int bh = idx >> 16;
    float denom = __uint_as_float(g_maxc) * __uint_as_float(g_maxr);
    g_z[((size_t)bh << 16) + (size_t)i * CM + j] =
        g_a2[((size_t)bh << 16) + (size_t)j * CM + i] / denom;
}

// ---------------------------------------------------------------------------
// Depthwise conv residual
// ---------------------------------------------------------------------------
__global__ void conv_res(const float* __restrict__ w) {
    int idx = blockIdx.x * 256 + threadIdx.x;
    int dh = idx & 63;
    int n  = (idx >> 6) & (CN - 1);
    int bh = idx >> 18;
    int h_ = bh & 7;
    size_t base = ((size_t)bh * CN) * CDH + dh;
    float s = 0.0f;
#pragma unroll
    for (int k = 0; k < 33; k++) {
        int nn = n + k - 16;
        if (nn >= 0 && nn < CN) s += w[h_ * 33 + k] * g_v[base + (size_t)nn * CDH];
    }
    g_outh[(size_t)idx] += s;
}

// ---------------------------------------------------------------------------
// Launch
// ---------------------------------------------------------------------------
extern "C" void kernel_launch(void* const* d_in, const int* in_sizes, int n_in,
                              void* d_out, int out_size) {
    const float* x     = (const float*)d_in[0];
    const float* gamma = (const float*)d_in[1];
    const float* beta  = (const float*)d_in[2];
    const float* Wqkv  = (const float*)d_in[3];
    const float* Wout  = (const float*)d_in[4];
    const float* bout  = (const float*)d_in[5];
    const float* convw = (const float*)d_in[6];
    float* out = (float*)d_out;

    float *xn, *q, *v, *kT, *ql, *klT, *a1, *a3, *a2;
    float *z, *z2, *xz, *tb, *ub, *av, *zav, *outh;
    void* p;
    cudaGetSymbolAddress(&p, g_xn);   xn   = (float*)p;
    cudaGetSymbolAddress(&p, g_q);    q    = (float*)p;
    cudaGetSymbolAddress(&p, g_v);    v    = (float*)p;
    cudaGetSymbolAddress(&p, g_kT);   kT   = (float*)p;
    cudaGetSymbolAddress(&p, g_ql);   ql   = (float*)p;
    cudaGetSymbolAddress(&p, g_klT);  klT  = (float*)p;
    cudaGetSymbolAddress(&p, g_a1);   a1   = (float*)p;
    cudaGetSymbolAddress(&p, g_a3);   a3   = (float*)p;
    cudaGetSymbolAddress(&p, g_a2);   a2   = (float*)p;
    cudaGetSymbolAddress(&p, g_z);    z    = (float*)p;
    cudaGetSymbolAddress(&p, g_z2);   z2   = (float*)p;
    cudaGetSymbolAddress(&p, g_xz);   xz   = (float*)p;
    cudaGetSymbolAddress(&p, g_t);    tb   = (float*)p;
    cudaGetSymbolAddress(&p, g_u);    ub   = (float*)p;
    cudaGetSymbolAddress(&p, g_av);   av   = (float*)p;
    cudaGetSymbolAddress(&p, g_zav);  zav  = (float*)p;
    cudaGetSymbolAddress(&p, g_outh); outh = (float*)p;

    const size_t MM = (size_t)CM * CM;
    const size_t NDH = (size_t)CN * CDH;

    // 1) LayerNorm
    ln_kernel<<<CB * CN, 128>>>(x, gamma, beta);

    // 2) QKV projection fused with head split/scale/transpose
    tc_gemm<128, 1><<<dim3(CT3 / 128, CB * CN / 128, 1), 256>>>(
        xn, Wqkv, xn, CD, CD, CT3, 0, 0, 0, 0,
        1.0f, 0.0f, 1.0f, nullptr, nullptr);

    // 3) Landmarks
    landmark_kernel<<<(CBH * CM * CDH) / 256, 256>>>();

    // 4) Similarities
    tc_gemm<128, 0><<<dim3(CM / 128, CN / 128, CBH), 256>>>(
        q, klT, a1, CDH, CDH, CM, CM,
        NDH, (size_t)CDH * CM, (size_t)CN * CM, 1.0f, 0.0f, 1.0f, nullptr, nullptr);
    tc_gemm<128, 0><<<dim3(CM / 128, CM / 128, CBH), 256>>>(
        ql, klT, a2, CDH, CDH, CM, CM,
        (size_t)CM * CDH, (size_t)CDH * CM, MM, 1.0f, 0.0f, 1.0f, nullptr, nullptr);
    tc_gemm<128, 0><<<dim3(CN / 128, CM / 128, CBH), 256>>>(
        ql, kT, a3, CDH, CDH, CN, CN,
        (size_t)CM * CDH, (size_t)CDH * CN, (size_t)CM * CN, 1.0f, 0.0f, 1.0f,
        nullptr, nullptr);

    // 5) Softmaxes
    softmax_rows<1><<<CBH * CN, 256>>>(a1, CM);
    softmax_rows<1><<<CBH * CM, 256>>>(a2, CM);
    softmax_rows<16><<<CBH * CM, 256>>>(a3, CN);

    // 6) Moore-Penrose pinv (6 Newton iterations, tf32 tensor-core GEMMs)
    init_scalars<<<1, 1>>>();
    absmax_sums<<<CBH, 256>>>();
    zinit_kernel<<<(CBH * CM * CM) / 256, 256>>>();
    float* zc = z;
    float* zn = z2;
    for (int it = 0; it < 6; it++) {
        tc_gemm<128, 0><<<dim3(2, 2, CBH), 256>>>(
            a2, zc, xz, CM, CM, CM, CM, MM, MM, MM, 1.0f, 0.0f, 1.0f, nullptr, nullptr);
        tc_gemm<128, 0><<<dim3(2, 2, CBH), 256>>>(
            xz, xz, tb, CM, CM, CM, CM, MM, MM, MM, 1.0f, 7.0f, -1.0f, nullptr, nullptr);
        tc_gemm<128, 0><<<dim3(2, 2, CBH), 256>>>(
            xz, tb, ub, CM, CM, CM, CM, MM, MM, MM, 1.0f, 15.0f, -1.0f, nullptr, nullptr);
        tc_gemm<128, 0><<<dim3(2, 2, CBH), 256>>>(
            zc, ub, zn, CM, CM, CM, CM, MM, MM, MM, 0.25f, 13.0f, -1.0f, nullptr, nullptr);
        float* tmp = zc; zc = zn; zn = tmp;
    }

    // 7) av = attn3 @ v
    tc_gemm<64, 0><<<dim3(1, CM / 128, CBH), 256>>>(
        a3, v, av, CN, CN, CDH, CDH,
        (size_t)CM * CN, NDH, (size_t)CM * CDH, 1.0f, 0.0f, 1.0f, nullptr, nullptr);

    // 8) zav = z @ av
    tc_gemm<64, 0><<<dim3(1, CM / 128, CBH), 256>>>(
        zc, av, zav, CM, CM, CDH, CDH,
        MM, (size_t)CM * CDH, (size_t)CM * CDH, 1.0f, 0.0f, 1.0f, nullptr, nullptr);

    // 9) outh = attn1 @ zav
    tc_gemm<64, 0><<<dim3(1, CN / 128, CBH), 256>>>(
        a1, zav, outh, CM, CM, CDH, CDH,
        (size_t)CN * CM, (size_t)CM * CDH, NDH, 1.0f, 0.0f, 1.0f, nullptr, nullptr);

    // 10) depthwise conv residual
    conv_res<<<(CBH * CN * CDH) / 256, 256>>>(convw);

    // 11) final projection + bias + residual (gather-A epilogue)
    tc_gemm<128, 2><<<dim3(CD / 128, CB * CN / 128, 1), 256>>>(
        outh, Wout, out, CD, 0, CD, CD, 0, 0, 0,
        1.0f, 0.0f, 1.0f, x, bout);
}

// round 3
// speedup vs baseline: 3.1244x; 1.6929x over previous
#include <cuda_runtime.h>
#include <cuda_bf16.h>
#include <math.h>
#include <stdint.h>

constexpr int CB  = 4;
constexpr int CN  = 4096;
constexpr int CD  = 512;
constexpr int CH  = 8;
constexpr int CDH = 64;
constexpr int CM  = 256;
constexpr int CL  = 16;
constexpr int CBH = CB * CH;    // 32
constexpr int CT3 = 3 * CD;     // 1536
constexpr float EPS = 1e-5f;

typedef __nv_bfloat16 bf16;
typedef __nv_bfloat162 bf162;

// ---------------------------------------------------------------------------
// Device scratch
// ---------------------------------------------------------------------------
__device__ __align__(16) bf16 g_xn  [(size_t)CB * CN * CD];
__device__ __align__(16) bf16 g_q   [(size_t)CBH * CN * CDH];
__device__ __align__(16) bf16 g_k   [(size_t)CBH * CN * CDH];
__device__ __align__(16) bf16 g_v   [(size_t)CBH * CN * CDH];
__device__ __align__(16) bf16 g_kT  [(size_t)CBH * CDH * CN];
__device__ __align__(16) bf16 g_ql  [(size_t)CBH * CM * CDH];
__device__ __align__(16) bf16 g_klT [(size_t)CBH * CDH * CM];
__device__ __align__(16) bf16 g_a1  [(size_t)CBH * CN * CM];
__device__ __align__(16) bf16 g_a3  [(size_t)CBH * CM * CN];
__device__ __align__(16) bf16 g_a2  [(size_t)CBH * CM * CM];
__device__ __align__(16) bf16 g_z   [(size_t)CBH * CM * CM];
__device__ __align__(16) bf16 g_z2  [(size_t)CBH * CM * CM];
__device__ __align__(16) bf16 g_xz  [(size_t)CBH * CM * CM];
__device__ __align__(16) bf16 g_t   [(size_t)CBH * CM * CM];
__device__ __align__(16) bf16 g_u   [(size_t)CBH * CM * CM];
__device__ __align__(16) bf16 g_av  [(size_t)CBH * CM * CDH];
__device__ __align__(16) bf16 g_zav [(size_t)CBH * CM * CDH];
__device__ __align__(16) bf16 g_outh[(size_t)CBH * CN * CDH];
__device__ unsigned g_maxc, g_maxr;

// ---------------------------------------------------------------------------
// helpers
// ---------------------------------------------------------------------------
__device__ __forceinline__ uint32_t pack2(float a, float b) {
    bf162 h = __floats2bfloat162_rn(a, b);
    return *reinterpret_cast<uint32_t*>(&h);
}
__device__ __forceinline__ float2 unpk(uint32_t u) {
    bf162 h = *reinterpret_cast<bf162*>(&u);
    return __bfloat1622float2(h);
}
__device__ __forceinline__ void mma16(float* c, const uint32_t* a,
                                      uint32_t b0, uint32_t b1) {
    asm volatile(
        "mma.sync.aligned.m16n8k16.row.col.f32.bf16.bf16.f32 "
        "{%0,%1,%2,%3},{%4,%5,%6,%7},{%8,%9},{%0,%1,%2,%3};"
        : "+f"(c[0]), "+f"(c[1]), "+f"(c[2]), "+f"(c[3])
        : "r"(a[0]), "r"(a[1]), "r"(a[2]), "r"(a[3]), "r"(b0), "r"(b1));
}

// ---------------------------------------------------------------------------
// bf16 tensor-core batched GEMM.  C = alpha * A @ (diagc*I + bsign*B)
// BK=32, 256 threads, 8 warps as 4x2. Warp tile (BM/4) x (BN/2).
// MODE 0: bf16 store   MODE 1: QKV scatter   MODE 2: final (gather A, +X+bias)
// ABF/BBF: operand in gmem is bf16 (else fp32, converted at staging).
// ---------------------------------------------------------------------------
template <int BM, int BN, int MODE, bool ABF, bool BBF, bool DIAG>
__global__ __launch_bounds__(256)
void tc_gemm(const void* __restrict__ Ap, const void* __restrict__ Bp,
             void* __restrict__ Cp,
             int K, int lda, int ldb, int ldc,
             size_t sA, size_t sB, size_t sC,
             float alpha, float diagc, float bsign,
             const float* __restrict__ X, const float* __restrict__ bias) {
    constexpr int WROWS = BM / 4;       // rows per warp tile
    constexpr int MI    = WROWS / 16;   // m16 frags per warp
    constexpr int WN    = BN / 2;
    constexpr int NFR   = WN / 8;
    constexpr int TPRA  = 256 / BM;     // threads per A row
    constexpr int KSPAN = 32 / TPRA;    // 16 or 8
    constexpr int TPRB  = BN / 4;       // threads per B pair-row
    constexpr int RPP   = 256 / TPRB;   // pair-rows per pass
    constexpr int BPASS = 16 / RPP;     // 2 or 1
    constexpr int AP    = 40;           // A pitch (halves)
    constexpr int BP    = BN + 8;       // B pitch (words)

    __shared__ bf16     As[BM * AP];
    __shared__ uint32_t Bs[16 * BP];

    const int t = threadIdx.x, warp = t >> 5, lane = t & 31;
    const int wm = warp >> 1, wn = warp & 1;
    const int g = lane >> 2, tg = lane & 3;
    const int rowBase = blockIdx.y * BM;
    const int colBase = blockIdx.x * BN;
    const int arow = t % BM, akg = (t / BM) * KSPAN;
    const int bcol = (t % TPRB) * 4, bk0 = t / TPRB;

    const bf16*  Ab16 = (const bf16*)Ap + blockIdx.z * sA;
    const float* Abf  = (const float*)Ap + blockIdx.z * sA;
    const bf16*  Bb16 = (const bf16*)Bp + blockIdx.z * sB;
    const float* Bbf  = (const float*)Bp + blockIdx.z * sB;

    uint4  pab[KSPAN / 8 > 0 ? KSPAN / 8 : 1];
    float4 paf[KSPAN / 4];
    uint2  pbb0[BPASS], pbb1[BPASS];
    float4 pbf0[BPASS], pbf1[BPASS];

    auto ldA = [&](int k0) {
        if (MODE == 2) {
            int r = rowBase + arow;
            int b_ = r >> 12, n = r & (CN - 1);
            int c = k0 + akg;
            int h_ = c >> 6, dh = c & 63;
            const bf16* p = Ab16 + ((((size_t)(b_ * CH + h_)) * CN + n) * CDH + dh);
#pragma unroll
            for (int i = 0; i < KSPAN / 8; i++)
                pab[i] = *(const uint4*)(p + i * 8);
        } else if (ABF) {
            const bf16* p = Ab16 + (size_t)(rowBase + arow) * lda + k0 + akg;
#pragma unroll
            for (int i = 0; i < KSPAN / 8; i++)
                pab[i] = *(const uint4*)(p + i * 8);
        } else {
            const float* p = Abf + (size_t)(rowBase + arow) * lda + k0 + akg;
#pragma unroll
            for (int i = 0; i < KSPAN / 4; i++)
                paf[i] = *(const float4*)(p + i * 4);
        }
    };
    auto ldB = [&](int k0) {
#pragma unroll
        for (int i = 0; i < BPASS; i++) {
            int kr = k0 + 2 * (bk0 + i * RPP);
            if (BBF) {
                pbb0[i] = *(const uint2*)(Bb16 + (size_t)kr * ldb + colBase + bcol);
                pbb1[i] = *(const uint2*)(Bb16 + (size_t)(kr + 1) * ldb + colBase + bcol);
            } else {
                pbf0[i] = *(const float4*)(Bbf + (size_t)kr * ldb + colBase + bcol);
                pbf1[i] = *(const float4*)(Bbf + (size_t)(kr + 1) * ldb + colBase + bcol);
            }
        }
    };
    auto stage = [&](int k0) {
        // A
        if (ABF || MODE == 2) {
#pragma unroll
            for (int i = 0; i < KSPAN / 8; i++)
                *(uint4*)&As[arow * AP + akg + i * 8] = pab[i];
        } else {
#pragma unroll
            for (int i = 0; i < KSPAN / 8; i++) {
                uint4 u;
                u.x = pack2(paf[i * 2].x, paf[i * 2].y);
                u.y = pack2(paf[i * 2].z, paf[i * 2].w);
                u.z = pack2(paf[i * 2 + 1].x, paf[i * 2 + 1].y);
                u.w = pack2(paf[i * 2 + 1].z, paf[i * 2 + 1].w);
                *(uint4*)&As[arow * AP + akg + i * 8] = u;
            }
        }
        // B
#pragma unroll
        for (int i = 0; i < BPASS; i++) {
            int kp = bk0 + i * RPP;
            uint4 u;
            if (BBF && !DIAG) {
                u.x = __byte_perm(pbb0[i].x, pbb1[i].x, 0x5410);
                u.y = __byte_perm(pbb0[i].x, pbb1[i].x, 0x7632);
                u.z = __byte_perm(pbb0[i].y, pbb1[i].y, 0x5410);
                u.w = __byte_perm(pbb0[i].y, pbb1[i].y, 0x7632);
            } else {
                float e[4], o[4];
                if (BBF) {
                    float2 f;
                    f = unpk(pbb0[i].x); e[0] = f.x; e[1] = f.y;
                    f = unpk(pbb0[i].y); e[2] = f.x; e[3] = f.y;
                    f = unpk(pbb1[i].x); o[0] = f.x; o[1] = f.y;
                    f = unpk(pbb1[i].y); o[2] = f.x; o[3] = f.y;
                } else {
                    e[0] = pbf0[i].x; e[1] = pbf0[i].y; e[2] = pbf0[i].z; e[3] = pbf0[i].w;
                    o[0] = pbf1[i].x; o[1] = pbf1[i].y; o[2] = pbf1[i].z; o[3] = pbf1[i].w;
                }
                if (DIAG) {
                    int kr = k0 + 2 * kp;
                    int cb = colBase + bcol;
#pragma unroll
                    for (int j = 0; j < 4; j++) {
                        e[j] = bsign * e[j] + ((kr == cb + j) ? diagc : 0.0f);
                        o[j] = bsign * o[j] + ((kr + 1 == cb + j) ? diagc : 0.0f);
                    }
                }
                u.x = pack2(e[0], o[0]);
                u.y = pack2(e[1], o[1]);
                u.z = pack2(e[2], o[2]);
                u.w = pack2(e[3], o[3]);
            }
            *(uint4*)&Bs[kp * BP + bcol] = u;
        }
    };

    float acc[MI][NFR][4] = {};

    ldA(0); ldB(0); stage(0);
    __syncthreads();
    for (int k0 = 0;; k0 += 32) {
        const int kn = k0 + 32;
        const bool more = kn < K;
        if (more) { ldA(kn); ldB(kn); }
#pragma unroll
        for (int ks = 0; ks < 2; ks++) {
            uint32_t af[MI][4];
#pragma unroll
            for (int mi = 0; mi < MI; mi++) {
                int base = (wm * WROWS + mi * 16 + g) * AP + ks * 16 + 2 * tg;
                af[mi][0] = *(const uint32_t*)&As[base];
                af[mi][1] = *(const uint32_t*)&As[base + 8 * AP];
                af[mi][2] = *(const uint32_t*)&As[base + 8];
                af[mi][3] = *(const uint32_t*)&As[base + 8 * AP + 8];
            }
#pragma unroll
            for (int ni = 0; ni < NFR; ni++) {
                int bidx = (ks * 8 + tg) * BP + wn * WN + ni * 8 + g;
                uint32_t b0 = Bs[bidx];
                uint32_t b1 = Bs[bidx + 4 * BP];
#pragma unroll
                for (int mi = 0; mi < MI; mi++)
                    mma16(acc[mi][ni], af[mi], b0, b1);
            }
        }
        if (!more) break;
        __syncthreads();
        stage(kn);
        __syncthreads();
    }

    // epilogue
    bf16*  Cb16 = (bf16*)Cp + blockIdx.z * sC;
    float* Cbf  = (float*)Cp + blockIdx.z * sC;
#pragma unroll
    for (int mi = 0; mi < MI; mi++)
#pragma unroll
        for (int ni = 0; ni < NFR; ni++) {
            int r0 = rowBase + wm * WROWS + mi * 16 + g;
            int c0 = colBase + wn * WN + ni * 8 + 2 * tg;
#pragma unroll
            for (int h2 = 0; h2 < 2; h2++) {
                int r = r0 + h2 * 8;
                float vx = alpha * acc[mi][ni][h2 * 2];
                float vy = alpha * acc[mi][ni][h2 * 2 + 1];
                if (MODE == 0) {
                    *(uint32_t*)&Cb16[(size_t)r * ldc + c0] = pack2(vx, vy);
                } else if (MODE == 1) {
                    int b_ = r >> 12, n = r & (CN - 1);
                    int which = c0 >> 9, inner = c0 & 511;
                    int h_ = inner >> 6, dh = inner & 63;
                    size_t off = (((size_t)(b_ * CH + h_)) * CN + n) * CDH + dh;
                    if (which == 0) {
                        *(uint32_t*)&g_q[off] = pack2(vx * 0.125f, vy * 0.125f);
                    } else if (which == 1) {
                        *(uint32_t*)&g_k[off] = pack2(vx, vy);
                        size_t ot = (((size_t)(b_ * CH + h_)) * CDH + dh) * CN + n;
                        g_kT[ot]      = __float2bfloat16(vx);
                        g_kT[ot + CN] = __float2bfloat16(vy);
                    } else {
                        *(uint32_t*)&g_v[off] = pack2(vx, vy);
                    }
                } else {
                    size_t o = (size_t)r * CD + c0;
                    float2 xr = *(const float2*)&X[o];
                    float2 br = *(const float2*)&bias[c0];
                    *(float2*)&Cbf[o] = make_float2(vx + xr.x + br.x,
                                                    vy + xr.y + br.y);
                }
            }
        }
}

// ---------------------------------------------------------------------------
// LayerNorm -> bf16
// ---------------------------------------------------------------------------
__global__ void ln_kernel(const float* __restrict__ x,
                          const float* __restrict__ gamma,
                          const float* __restrict__ beta) {
    int row = blockIdx.x;
    int t = threadIdx.x;  // 128
    const float4* xr = (const float4*)(x + (size_t)row * CD);
    float4 v = xr[t];
    float s  = v.x + v.y + v.z + v.w;
    float ss = v.x * v.x + v.y * v.y + v.z * v.z + v.w * v.w;
    __shared__ float shs[4], shss[4];
#pragma unroll
    for (int o = 16; o > 0; o >>= 1) {
        s  += __shfl_down_sync(0xffffffffu, s,  o);
        ss += __shfl_down_sync(0xffffffffu, ss, o);
    }
    int wid = t >> 5, lane = t & 31;
    if (!lane) { shs[wid] = s; shss[wid] = ss; }
    __syncthreads();
    s  = shs[0]  + shs[1]  + shs[2]  + shs[3];
    ss = shss[0] + shss[1] + shss[2] + shss[3];
    float mean = s * (1.0f / CD);
    float var  = ss * (1.0f / CD) - mean * mean;
    float inv  = rsqrtf(var + EPS);
    float4 gg = ((const float4*)gamma)[t];
    float4 bb = ((const float4*)beta)[t];
    uint2 o;
    o.x = pack2((v.x - mean) * inv * gg.x + bb.x, (v.y - mean) * inv * gg.y + bb.y);
    o.y = pack2((v.z - mean) * inv * gg.z + bb.z, (v.w - mean) * inv * gg.w + bb.w);
    *(uint2*)&g_xn[(size_t)row * CD + t * 4] = o;
}

// ---------------------------------------------------------------------------
// Landmark means
// ---------------------------------------------------------------------------
__global__ void landmark_kernel() {
    int idx = blockIdx.x * 256 + threadIdx.x;  // BH*M*DH
    int dh = idx & 63;
    int mi = (idx >> 6) & 255;
    int bh = idx >> 14;
    size_t base = ((size_t)bh * CN + mi * CL) * CDH + dh;
    float sq = 0.0f, sk = 0.0f;
#pragma unroll
    for (int j = 0; j < CL; j++) {
        sq += __bfloat162float(g_q[base + (size_t)j * CDH]);
        sk += __bfloat162float(g_k[base + (size_t)j * CDH]);
    }
    g_ql [((size_t)bh * CM + mi) * CDH + dh] = __float2bfloat16(sq * (1.0f / CL));
    g_klT[((size_t)bh * CDH + dh) * CM + mi] = __float2bfloat16(sk * (1.0f / CL));
}

// ---------------------------------------------------------------------------
// Row softmax (bf16 in/out, fp32 math)
// ---------------------------------------------------------------------------
template <int IT>
__global__ void softmax_rows(bf16* __restrict__ p, int len) {
    bf16* r = p + (size_t)blockIdx.x * len;
    int t = threadIdx.x;
    float vals[IT];
    float mx = -3.4e38f;
#pragma unroll
    for (int i = 0; i < IT; i++) {
        vals[i] = __bfloat162float(r[t + i * 256]);
        mx = fmaxf(mx, vals[i]);
    }
    __shared__ float sh[8];
#pragma unroll
    for (int o = 16; o > 0; o >>= 1) mx = fmaxf(mx, __shfl_xor_sync(0xffffffffu, mx, o));
    int wid = t >> 5, lane = t & 31;
    if (!lane) sh[wid] = mx;
    __syncthreads();
    mx = sh[0];
#pragma unroll
    for (int w = 1; w < 8; w++) mx = fmaxf(mx, sh[w]);
    __syncthreads();
    float s = 0.0f;
#pragma unroll
    for (int i = 0; i < IT; i++) {
        vals[i] = expf(vals[i] - mx);
        s += vals[i];
    }
#pragma unroll
    for (int o = 16; o > 0; o >>= 1) s += __shfl_xor_sync(0xffffffffu, s, o);
    if (!lane) sh[wid] = s;
    __syncthreads();
    s = sh[0];
#pragma unroll
    for (int w = 1; w < 8; w++) s += sh[w];
    float inv = 1.0f / s;
#pragma unroll
    for (int i = 0; i < IT; i++) r[t + i * 256] = __float2bfloat16(vals[i] * inv);
}

// ---------------------------------------------------------------------------
// Pinv init
// ---------------------------------------------------------------------------
__global__ void init_scalars() { g_maxc = 0u; g_maxr = 0u; }

__global__ void absmax_sums() {
    int bh = blockIdx.x;
    int t = threadIdx.x;
    const bf16* a = g_a2 + (size_t)bh * CM * CM;
    float rs = 0.0f, cs = 0.0f;
    for (int j = 0; j < CM; j++) rs += fabsf(__bfloat162float(a[(size_t)t * CM + j]));
    for (int i = 0; i < CM; i++) cs += fabsf(__bfloat162float(a[(size_t)i * CM + t]));
    atomicMax(&g_maxc, __float_as_uint(rs));
    atomicMax(&g_maxr, __float_as_uint(cs));
}

__global__ void zinit_kernel() {
    int idx = blockIdx.x * 256 + threadIdx.x;
    int j = idx & 255;
    int i = (idx >> 8) & 255;
    int bh = idx >> 16;
    float denom = __uint_as_float(g_maxc) * __uint_as_float(g_maxr);
    g_z[((size_t)bh << 16) + (size_t)i * CM + j] =
        __float2bfloat16(__bfloat162float(g_a2[((size_t)bh << 16) + (size_t)j * CM + i]) / denom);
}

// ---------------------------------------------------------------------------
// Depthwise conv residual (sliding window, 4 outputs/thread)
// ---------------------------------------------------------------------------
__global__ void conv_res(const float* __restrict__ w) {
    __shared__ float ws[33];
    int idx = blockIdx.x * 256 + threadIdx.x;
    int dh = idx & 63;
    int nq = (idx >> 6) & 1023;   // CN/4
    int bh = idx >> 16;
    int h_ = bh & 7;
    if (threadIdx.x < 33) ws[threadIdx.x] = w[h_ * 33 + threadIdx.x];
    __syncthreads();
    int n0 = nq * 4;
    size_t base = ((size_t)bh * CN) * CDH + dh;
    float vv[36];
#pragma unroll
    for (int j = 0; j < 36; j++) {
        int nn = n0 - 16 + j;
        vv[j] = (nn >= 0 && nn < CN)
                    ? __bfloat162float(g_v[base + (size_t)nn * CDH]) : 0.0f;
    }
#pragma unroll
    for (int i = 0; i < 4; i++) {
        float s = 0.0f;
#pragma unroll
        for (int k2 = 0; k2 < 33; k2++) s += ws[k2] * vv[k2 + i];
        size_t o = base + (size_t)(n0 + i) * CDH;
        g_outh[o] = __float2bfloat16(__bfloat162float(g_outh[o]) + s);
    }
}

// ---------------------------------------------------------------------------
// Launch
// ---------------------------------------------------------------------------
extern "C" void kernel_launch(void* const* d_in, const int* in_sizes, int n_in,
                              void* d_out, int out_size) {
    const float* x     = (const float*)d_in[0];
    const float* gamma = (const float*)d_in[1];
    const float* beta  = (const float*)d_in[2];
    const float* Wqkv  = (const float*)d_in[3];
    const float* Wout  = (const float*)d_in[4];
    const float* bout  = (const float*)d_in[5];
    const float* convw = (const float*)d_in[6];
    float* out = (float*)d_out;

    bf16 *xn, *q, *v, *kT, *ql, *klT, *a1, *a3, *a2;
    bf16 *z, *z2, *xz, *tb, *ub, *av, *zav, *outh;
    void* p;
    cudaGetSymbolAddress(&p, g_xn);   xn   = (bf16*)p;
    cudaGetSymbolAddress(&p, g_q);    q    = (bf16*)p;
    cudaGetSymbolAddress(&p, g_v);    v    = (bf16*)p;
    cudaGetSymbolAddress(&p, g_kT);   kT   = (bf16*)p;
    cudaGetSymbolAddress(&p, g_ql);   ql   = (bf16*)p;
    cudaGetSymbolAddress(&p, g_klT);  klT  = (bf16*)p;
    cudaGetSymbolAddress(&p, g_a1);   a1   = (bf16*)p;
    cudaGetSymbolAddress(&p, g_a3);   a3   = (bf16*)p;
    cudaGetSymbolAddress(&p, g_a2);   a2   = (bf16*)p;
    cudaGetSymbolAddress(&p, g_z);    z    = (bf16*)p;
    cudaGetSymbolAddress(&p, g_z2);   z2   = (bf16*)p;
    cudaGetSymbolAddress(&p, g_xz);   xz   = (bf16*)p;
    cudaGetSymbolAddress(&p, g_t);    tb   = (bf16*)p;
    cudaGetSymbolAddress(&p, g_u);    ub   = (bf16*)p;
    cudaGetSymbolAddress(&p, g_av);   av   = (bf16*)p;
    cudaGetSymbolAddress(&p, g_zav);  zav  = (bf16*)p;
    cudaGetSymbolAddress(&p, g_outh); outh = (bf16*)p;

    const size_t MM  = (size_t)CM * CM;
    const size_t NDH = (size_t)CN * CDH;

    // 1) LayerNorm
    ln_kernel<<<CB * CN, 128>>>(x, gamma, beta);

    // 2) QKV projection fused with head split/scale/transpose (A,B fp32)
    tc_gemm<128, 128, 1, true, false, false><<<dim3(CT3 / 128, CB * CN / 128, 1), 256>>>(
        xn, Wqkv, nullptr, CD, CD, CT3, 0, 0, 0, 0, 1.0f, 0.0f, 1.0f, nullptr, nullptr);

    // 3) Landmarks
    landmark_kernel<<<(CBH * CM * CDH) / 256, 256>>>();

    // 4) Similarities
    tc_gemm<128, 128, 0, true, true, false><<<dim3(CM / 128, CN / 128, CBH), 256>>>(
        q, klT, a1, CDH, CDH, CM, CM,
        NDH, (size_t)CDH * CM, (size_t)CN * CM, 1.0f, 0.0f, 1.0f, nullptr, nullptr);
    tc_gemm<64, 128, 0, true, true, false><<<dim3(CM / 128, CM / 64, CBH), 256>>>(
        ql, klT, a2, CDH, CDH, CM, CM,
        (size_t)CM * CDH, (size_t)CDH * CM, MM, 1.0f, 0.0f, 1.0f, nullptr, nullptr);
    tc_gemm<128, 128, 0, true, true, false><<<dim3(CN / 128, CM / 128, CBH), 256>>>(
        ql, kT, a3, CDH, CDH, CN, CN,
        (size_t)CM * CDH, (size_t)CDH * CN, (size_t)CM * CN, 1.0f, 0.0f, 1.0f,
        nullptr, nullptr);

    // 5) Softmaxes
    softmax_rows<1><<<CBH * CN, 256>>>(a1, CM);
    softmax_rows<1><<<CBH * CM, 256>>>(a2, CM);
    softmax_rows<16><<<CBH * CM, 256>>>(a3, CN);

    // 6) Moore-Penrose pinv (6 Newton iterations)
    init_scalars<<<1, 1>>>();
    absmax_sums<<<CBH, 256>>>();
    zinit_kernel<<<(CBH * CM * CM) / 256, 256>>>();
    bf16* zc = z;
    bf16* zn = z2;
    for (int it = 0; it < 6; it++) {
        tc_gemm<64, 128, 0, true, true, false><<<dim3(2, 4, CBH), 256>>>(
            a2, zc, xz, CM, CM, CM, CM, MM, MM, MM, 1.0f, 0.0f, 1.0f, nullptr, nullptr);
        tc_gemm<64, 128, 0, true, true, true><<<dim3(2, 4, CBH), 256>>>(
            xz, xz, tb, CM, CM, CM, CM, MM, MM, MM, 1.0f, 7.0f, -1.0f, nullptr, nullptr);
        tc_gemm<64, 128, 0, true, true, true><<<dim3(2, 4, CBH), 256>>>(
            xz, tb, ub, CM, CM, CM, CM, MM, MM, MM, 1.0f, 15.0f, -1.0f, nullptr, nullptr);
        tc_gemm<64, 128, 0, true, true, true><<<dim3(2, 4, CBH), 256>>>(
            zc, ub, zn, CM, CM, CM, CM, MM, MM, MM, 0.25f, 13.0f, -1.0f, nullptr, nullptr);
        bf16* tmp = zc; zc = zn; zn = tmp;
    }

    // 7) av = attn3 @ v
    tc_gemm<64, 64, 0, true, true, false><<<dim3(1, CM / 64, CBH), 256>>>(
        a3, v, av, CN, CN, CDH, CDH,
        (size_t)CM * CN, NDH, (size_t)CM * CDH, 1.0f, 0.0f, 1.0f, nullptr, nullptr);

    // 8) zav = z @ av
    tc_gemm<64, 64, 0, true, true, false><<<dim3(1, CM / 64, CBH), 256>>>(
        zc, av, zav, CM, CM, CDH, CDH,
        MM, (size_t)CM * CDH, (size_t)CM * CDH, 1.0f, 0.0f, 1.0f, nullptr, nullptr);

    // 9) outh = attn1 @ zav
    tc_gemm<128, 64, 0, true, true, false><<<dim3(1, CN / 128, CBH), 256>>>(
        a1, zav, outh, CM, CM, CDH, CDH,
        (size_t)CN * CM, (size_t)CM * CDH, NDH, 1.0f, 0.0f, 1.0f, nullptr, nullptr);

    // 10) depthwise conv residual
    conv_res<<<(CBH * CN * CDH) / 1024, 256>>>(convw);

    // 11) final projection + bias + residual (gather-A epilogue)
    tc_gemm<128, 128, 2, true, false, false><<<dim3(CD / 128, CB * CN / 128, 1), 256>>>(
        outh, Wout, out, CD, 0, CD, CD, 0, 0, 0, 1.0f, 0.0f, 1.0f, x, bout);
}

// round 4
// speedup vs baseline: 3.3623x; 1.0761x over previous
#include <cuda_runtime.h>
#include <cuda_bf16.h>
#include <math.h>
#include <stdint.h>

constexpr int CB  = 4;
constexpr int CN  = 4096;
constexpr int CD  = 512;
constexpr int CH  = 8;
constexpr int CDH = 64;
constexpr int CM  = 256;
constexpr int CL  = 16;
constexpr int CBH = CB * CH;    // 32
constexpr int CT3 = 3 * CD;     // 1536
constexpr float EPS = 1e-5f;

typedef __nv_bfloat16 bf16;
typedef __nv_bfloat162 bf162;

// ---------------------------------------------------------------------------
// Device scratch
// ---------------------------------------------------------------------------
__device__ __align__(16) bf16 g_xn  [(size_t)CB * CN * CD];
__device__ __align__(16) bf16 g_q   [(size_t)CBH * CN * CDH];
__device__ __align__(16) bf16 g_k   [(size_t)CBH * CN * CDH];
__device__ __align__(16) bf16 g_v   [(size_t)CBH * CN * CDH];
__device__ __align__(16) bf16 g_kT  [(size_t)CBH * CDH * CN];
__device__ __align__(16) bf16 g_ql  [(size_t)CBH * CM * CDH];
__device__ __align__(16) bf16 g_klT [(size_t)CBH * CDH * CM];
__device__ __align__(16) bf16 g_a1  [(size_t)CBH * CN * CM];
__device__ __align__(16) bf16 g_a3  [(size_t)CBH * CM * CN];
__device__ __align__(16) bf16 g_a2  [(size_t)CBH * CM * CM];
__device__ __align__(16) bf16 g_z   [(size_t)CBH * CM * CM];
__device__ __align__(16) bf16 g_z2  [(size_t)CBH * CM * CM];
__device__ __align__(16) bf16 g_xz  [(size_t)CBH * CM * CM];
__device__ __align__(16) bf16 g_t   [(size_t)CBH * CM * CM];
__device__ __align__(16) bf16 g_u   [(size_t)CBH * CM * CM];
__device__ __align__(16) bf16 g_av  [(size_t)CBH * CM * CDH];
__device__ __align__(16) bf16 g_zav [(size_t)CBH * CM * CDH];
__device__ __align__(16) bf16 g_outh[(size_t)CBH * CN * CDH];
__device__ unsigned g_maxc, g_maxr;

// ---------------------------------------------------------------------------
// helpers
// ---------------------------------------------------------------------------
__device__ __forceinline__ uint32_t pack2(float a, float b) {
    bf162 h = __floats2bfloat162_rn(a, b);
    return *reinterpret_cast<uint32_t*>(&h);
}
__device__ __forceinline__ float2 unpk(uint32_t u) {
    bf162 h = *reinterpret_cast<bf162*>(&u);
    return __bfloat1622float2(h);
}
__device__ __forceinline__ void mma16(float* c, const uint32_t* a,
                                      uint32_t b0, uint32_t b1) {
    asm volatile(
        "mma.sync.aligned.m16n8k16.row.col.f32.bf16.bf16.f32 "
        "{%0,%1,%2,%3},{%4,%5,%6,%7},{%8,%9},{%0,%1,%2,%3};"
        : "+f"(c[0]), "+f"(c[1]), "+f"(c[2]), "+f"(c[3])
        : "r"(a[0]), "r"(a[1]), "r"(a[2]), "r"(a[3]), "r"(b0), "r"(b1));
}
__device__ __forceinline__ void ldsm4(uint32_t* r, uint32_t addr) {
    asm volatile(
        "ldmatrix.sync.aligned.m8n8.x4.shared.b16 {%0,%1,%2,%3},[%4];"
        : "=r"(r[0]), "=r"(r[1]), "=r"(r[2]), "=r"(r[3]) : "r"(addr));
}
__device__ __forceinline__ void ldsm4t(uint32_t& r0, uint32_t& r1,
                                       uint32_t& r2, uint32_t& r3, uint32_t addr) {
    asm volatile(
        "ldmatrix.sync.aligned.m8n8.x4.trans.shared.b16 {%0,%1,%2,%3},[%4];"
        : "=r"(r0), "=r"(r1), "=r"(r2), "=r"(r3) : "r"(addr));
}

// ---------------------------------------------------------------------------
// bf16 tensor-core batched GEMM.  C = alpha * A @ (diagc*I + bsign*B)
// BK=32, 256 threads, 8 warps as 4x2. Warp tile (BM/4) x (BN/2).
// Fragment loads via ldmatrix (A: x4, B: x4.trans on row-major [k][col] smem).
// MODE 0: bf16 store   MODE 1: QKV scatter   MODE 2: final (gather A, +X+bias)
// BBF: B operand in gmem is bf16 (else fp32, converted at staging). A is bf16.
// ---------------------------------------------------------------------------
template <int BM, int BN, int MODE, bool BBF, bool DIAG>
__global__ __launch_bounds__(256, 2)
void tc_gemm(const void* __restrict__ Ap, const void* __restrict__ Bp,
             void* __restrict__ Cp,
             int K, int lda, int ldb, int ldc,
             size_t sA, size_t sB, size_t sC,
             float alpha, float diagc, float bsign,
             const float* __restrict__ X, const float* __restrict__ bias) {
    constexpr int WROWS = BM / 4;       // rows per warp tile
    constexpr int MI    = WROWS / 16;   // m16 frags per warp
    constexpr int WN    = BN / 2;
    constexpr int NFR   = WN / 8;
    constexpr int TPRA  = 256 / BM;     // threads per A row
    constexpr int KSPAN = 32 / TPRA;    // halves per thread (16 or 8)
    constexpr int NU4   = KSPAN / 8;    // uint4 loads per thread (2 or 1)
    constexpr int TPRB  = BN / 8;       // threads per B row (8 halves each)
    constexpr int RPPB  = 256 / TPRB;   // B rows per pass
    constexpr int BPASS = 32 / RPPB;    // passes (2 for BN=128, 1 for BN=64)
    constexpr int AP    = 40;           // A pitch (halves)
    constexpr int BPH   = BN + 8;       // B pitch (halves)

    __shared__ bf16 As[BM * AP];
    __shared__ bf16 Bs[32 * BPH];

    const int t = threadIdx.x, warp = t >> 5, lane = t & 31;
    const int wm = warp >> 1, wn = warp & 1;
    const int g = lane >> 2, tg = lane & 3;
    const int rowBase = blockIdx.y * BM;
    const int colBase = blockIdx.x * BN;
    const int arow = t % BM, akg = (t / BM) * KSPAN;
    const int brow = t / TPRB, bcol = (t % TPRB) * 8;

    const bf16*  Ab16 = (const bf16*)Ap + blockIdx.z * sA;
    const bf16*  Bb16 = (const bf16*)Bp + blockIdx.z * sB;
    const float* Bbf  = (const float*)Bp + blockIdx.z * sB;

    const uint32_t asb = (uint32_t)__cvta_generic_to_shared(As);
    const uint32_t bsb = (uint32_t)__cvta_generic_to_shared(Bs);
    // per-lane ldmatrix base offsets (bytes)
    const uint32_t aoff = asb +
        ((((lane >> 3) & 1) * 8 + (lane & 7)) * AP + (lane >> 4) * 8) * 2;
    const uint32_t boff = bsb +
        ((((lane >> 3) & 1) * 8 + (lane & 7)) * BPH + wn * WN + (lane >> 4) * 8) * 2;

    uint4  pa[NU4];
    uint4  pbb[BPASS];
    float4 pbf[BPASS][2];

    auto ldA = [&](int k0) {
        if (MODE == 2) {
            int r = rowBase + arow;
            int b_ = r >> 12, n = r & (CN - 1);
            int c = k0 + akg;
            int h_ = c >> 6, dh = c & 63;
            const bf16* p = Ab16 + ((((size_t)(b_ * CH + h_)) * CN + n) * CDH + dh);
#pragma unroll
            for (int i = 0; i < NU4; i++) pa[i] = *(const uint4*)(p + i * 8);
        } else {
            const bf16* p = Ab16 + (size_t)(rowBase + arow) * lda + k0 + akg;
#pragma unroll
            for (int i = 0; i < NU4; i++) pa[i] = *(const uint4*)(p + i * 8);
        }
    };
    auto ldB = [&](int k0) {
#pragma unroll
        for (int i = 0; i < BPASS; i++) {
            int kr = k0 + brow + i * RPPB;
            if (BBF) {
                pbb[i] = *(const uint4*)(Bb16 + (size_t)kr * ldb + colBase + bcol);
            } else {
                const float* p = Bbf + (size_t)kr * ldb + colBase + bcol;
                pbf[i][0] = *(const float4*)p;
                pbf[i][1] = *(const float4*)(p + 4);
            }
        }
    };
    auto stage = [&](int k0) {
#pragma unroll
        for (int i = 0; i < NU4; i++)
            *(uint4*)&As[arow * AP + akg + i * 8] = pa[i];
#pragma unroll
        for (int i = 0; i < BPASS; i++) {
            int r = brow + i * RPPB;
            uint4 u;
            if (BBF && !DIAG) {
                u = pbb[i];
            } else {
                float e[8];
                if (BBF) {
                    float2 f;
                    f = unpk(pbb[i].x); e[0] = f.x; e[1] = f.y;
                    f = unpk(pbb[i].y); e[2] = f.x; e[3] = f.y;
                    f = unpk(pbb[i].z); e[4] = f.x; e[5] = f.y;
                    f = unpk(pbb[i].w); e[6] = f.x; e[7] = f.y;
                } else {
                    e[0] = pbf[i][0].x; e[1] = pbf[i][0].y;
                    e[2] = pbf[i][0].z; e[3] = pbf[i][0].w;
                    e[4] = pbf[i][1].x; e[5] = pbf[i][1].y;
                    e[6] = pbf[i][1].z; e[7] = pbf[i][1].w;
                }
                if (DIAG) {
                    int kr = k0 + r;
                    int cb = colBase + bcol;
#pragma unroll
                    for (int j = 0; j < 8; j++)
                        e[j] = bsign * e[j] + ((kr == cb + j) ? diagc : 0.0f);
                }
                u.x = pack2(e[0], e[1]); u.y = pack2(e[2], e[3]);
                u.z = pack2(e[4], e[5]); u.w = pack2(e[6], e[7]);
            }
            *(uint4*)&Bs[r * BPH + bcol] = u;
        }
    };

    float acc[MI][NFR][4] = {};

    ldA(0); ldB(0); stage(0);
    __syncthreads();
    for (int k0 = 0;; k0 += 32) {
        const int kn = k0 + 32;
        const bool more = kn < K;
        if (more) { ldA(kn); ldB(kn); }
#pragma unroll
        for (int ks = 0; ks < 2; ks++) {
            uint32_t af[MI][4];
#pragma unroll
            for (int mi = 0; mi < MI; mi++)
                ldsm4(af[mi], aoff + ((wm * WROWS + mi * 16) * AP + ks * 16) * 2);
            uint32_t bf[NFR][2];
#pragma unroll
            for (int np = 0; np < NFR / 2; np++)
                ldsm4t(bf[2 * np][0], bf[2 * np][1],
                       bf[2 * np + 1][0], bf[2 * np + 1][1],
                       boff + (ks * 16 * BPH + np * 16) * 2);
#pragma unroll
            for (int ni = 0; ni < NFR; ni++)
#pragma unroll
                for (int mi = 0; mi < MI; mi++)
                    mma16(acc[mi][ni], af[mi], bf[ni][0], bf[ni][1]);
        }
        if (!more) break;
        __syncthreads();
        stage(kn);
        __syncthreads();
    }

    // epilogue
    bf16*  Cb16 = (bf16*)Cp + blockIdx.z * sC;
    float* Cbf  = (float*)Cp + blockIdx.z * sC;
#pragma unroll
    for (int mi = 0; mi < MI; mi++)
#pragma unroll
        for (int ni = 0; ni < NFR; ni++) {
            int r0 = rowBase + wm * WROWS + mi * 16 + g;
            int c0 = colBase + wn * WN + ni * 8 + 2 * tg;
#pragma unroll
            for (int h2 = 0; h2 < 2; h2++) {
                int r = r0 + h2 * 8;
                float vx = alpha * acc[mi][ni][h2 * 2];
                float vy = alpha * acc[mi][ni][h2 * 2 + 1];
                if (MODE == 0) {
                    *(uint32_t*)&Cb16[(size_t)r * ldc + c0] = pack2(vx, vy);
                } else if (MODE == 1) {
                    int b_ = r >> 12, n = r & (CN - 1);
                    int which = c0 >> 9, inner = c0 & 511;
                    int h_ = inner >> 6, dh = inner & 63;
                    size_t off = (((size_t)(b_ * CH + h_)) * CN + n) * CDH + dh;
                    if (which == 0) {
                        *(uint32_t*)&g_q[off] = pack2(vx * 0.125f, vy * 0.125f);
                    } else if (which == 1) {
                        *(uint32_t*)&g_k[off] = pack2(vx, vy);
                        size_t ot = (((size_t)(b_ * CH + h_)) * CDH + dh) * CN + n;
                        g_kT[ot]      = __float2bfloat16(vx);
                        g_kT[ot + CN] = __float2bfloat16(vy);
                    } else {
                        *(uint32_t*)&g_v[off] = pack2(vx, vy);
                    }
                } else {
                    size_t o = (size_t)r * CD + c0;
                    float2 xr = *(const float2*)&X[o];
                    float2 br = *(const float2*)&bias[c0];
                    *(float2*)&Cbf[o] = make_float2(vx + xr.x + br.x,
                                                    vy + xr.y + br.y);
                }
            }
        }
}

// ---------------------------------------------------------------------------
// LayerNorm -> bf16
// ---------------------------------------------------------------------------
__global__ void ln_kernel(const float* __restrict__ x,
                          const float* __restrict__ gamma,
                          const float* __restrict__ beta) {
    int row = blockIdx.x;
    int t = threadIdx.x;  // 128
    const float4* xr = (const float4*)(x + (size_t)row * CD);
    float4 v = xr[t];
    float s  = v.x + v.y + v.z + v.w;
    float ss = v.x * v.x + v.y * v.y + v.z * v.z + v.w * v.w;
    __shared__ float shs[4], shss[4];
#pragma unroll
    for (int o = 16; o > 0; o >>= 1) {
        s  += __shfl_down_sync(0xffffffffu, s,  o);
        ss += __shfl_down_sync(0xffffffffu, ss, o);
    }
    int wid = t >> 5, lane = t & 31;
    if (!lane) { shs[wid] = s; shss[wid] = ss; }
    __syncthreads();
    s  = shs[0]  + shs[1]  + shs[2]  + shs[3];
    ss = shss[0] + shss[1] + shss[2] + shss[3];
    float mean = s * (1.0f / CD);
    float var  = ss * (1.0f / CD) - mean * mean;
    float inv  = rsqrtf(var + EPS);
    float4 gg = ((const float4*)gamma)[t];
    float4 bb = ((const float4*)beta)[t];
    uint2 o;
    o.x = pack2((v.x - mean) * inv * gg.x + bb.x, (v.y - mean) * inv * gg.y + bb.y);
    o.y = pack2((v.z - mean) * inv * gg.z + bb.z, (v.w - mean) * inv * gg.w + bb.w);
    *(uint2*)&g_xn[(size_t)row * CD + t * 4] = o;
}

// ---------------------------------------------------------------------------
// Landmark means
// ---------------------------------------------------------------------------
__global__ void landmark_kernel() {
    int idx = blockIdx.x * 256 + threadIdx.x;  // BH*M*DH
    int dh = idx & 63;
    int mi = (idx >> 6) & 255;
    int bh = idx >> 14;
    size_t base = ((size_t)bh * CN + mi * CL) * CDH + dh;
    float sq = 0.0f, sk = 0.0f;
#pragma unroll
    for (int j = 0; j < CL; j++) {
        sq += __bfloat162float(g_q[base + (size_t)j * CDH]);
        sk += __bfloat162float(g_k[base + (size_t)j * CDH]);
    }
    g_ql [((size_t)bh * CM + mi) * CDH + dh] = __float2bfloat16(sq * (1.0f / CL));
    g_klT[((size_t)bh * CDH + dh) * CM + mi] = __float2bfloat16(sk * (1.0f / CL));
}

// ---------------------------------------------------------------------------
// Row softmax (bf16 in/out, fp32 math)
// ---------------------------------------------------------------------------
template <int IT>
__global__ void softmax_rows(bf16* __restrict__ p, int len) {
    bf16* r = p + (size_t)blockIdx.x * len;
    int t = threadIdx.x;
    float vals[IT];
    float mx = -3.4e38f;
#pragma unroll
    for (int i = 0; i < IT; i++) {
        vals[i] = __bfloat162float(r[t + i * 256]);
        mx = fmaxf(mx, vals[i]);
    }
    __shared__ float sh[8];
#pragma unroll
    for (int o = 16; o > 0; o >>= 1) mx = fmaxf(mx, __shfl_xor_sync(0xffffffffu, mx, o));
    int wid = t >> 5, lane = t & 31;
    if (!lane) sh[wid] = mx;
    __syncthreads();
    mx = sh[0];
#pragma unroll
    for (int w = 1; w < 8; w++) mx = fmaxf(mx, sh[w]);
    __syncthreads();
    float s = 0.0f;
#pragma unroll
    for (int i = 0; i < IT; i++) {
        vals[i] = expf(vals[i] - mx);
        s += vals[i];
    }
#pragma unroll
    for (int o = 16; o > 0; o >>= 1) s += __shfl_xor_sync(0xffffffffu, s, o);
    if (!lane) sh[wid] = s;
    __syncthreads();
    s = sh[0];
#pragma unroll
    for (int w = 1; w < 8; w++) s += sh[w];
    float inv = 1.0f / s;
#pragma unroll
    for (int i = 0; i < IT; i++) r[t + i * 256] = __float2bfloat16(vals[i] * inv);
}

// ---------------------------------------------------------------------------
// Pinv init
// ---------------------------------------------------------------------------
__global__ void init_scalars() { g_maxc = 0u; g_maxr = 0u; }

__global__ void absmax_sums() {
    int bh = blockIdx.x;
    int t = threadIdx.x;
    const bf16* a = g_a2 + (size_t)bh * CM * CM;
    float rs = 0.0f, cs = 0.0f;
    for (int j = 0; j < CM; j++) rs += fabsf(__bfloat162float(a[(size_t)t * CM + j]));
    for (int i = 0; i < CM; i++) cs += fabsf(__bfloat162float(a[(size_t)i * CM + t]));
    atomicMax(&g_maxc, __float_as_uint(rs));
    atomicMax(&g_maxr, __float_as_uint(cs));
}

__global__ void zinit_kernel() {
    int idx = blockIdx.x * 256 + threadIdx.x;
    int j = idx & 255;
    int i = (idx >> 8) & 255;
    int bh = idx >> 16;
    float denom = __uint_as_float(g_maxc) * __uint_as_float(g_maxr);
    g_z[((size_t)bh << 16) + (size_t)i * CM + j] =
        __float2bfloat16(__bfloat162float(g_a2[((size_t)bh << 16) + (size_t)j * CM + i]) / denom);
}

// ---------------------------------------------------------------------------
// Depthwise conv residual (sliding window, 4 outputs/thread)
// ---------------------------------------------------------------------------
__global__ void conv_res(const float* __restrict__ w) {
    __shared__ float ws[33];
    int idx = blockIdx.x * 256 + threadIdx.x;
    int dh = idx & 63;
    int nq = (idx >> 6) & 1023;   // CN/4
    int bh = idx >> 16;
    int h_ = bh & 7;
    if (threadIdx.x < 33) ws[threadIdx.x] = w[h_ * 33 + threadIdx.x];
    __syncthreads();
    int n0 = nq * 4;
    size_t base = ((size_t)bh * CN) * CDH + dh;
    float vv[36];
#pragma unroll
    for (int j = 0; j < 36; j++) {
        int nn = n0 - 16 + j;
        vv[j] = (nn >= 0 && nn < CN)
                    ? __bfloat162float(g_v[base + (size_t)nn * CDH]) : 0.0f;
    }
#pragma unroll
    for (int i = 0; i < 4; i++) {
        float s = 0.0f;
#pragma unroll
        for (int k2 = 0; k2 < 33; k2++) s += ws[k2] * vv[k2 + i];
        size_t o = base + (size_t)(n0 + i) * CDH;
        g_outh[o] = __float2bfloat16(__bfloat162float(g_outh[o]) + s);
    }
}

// ---------------------------------------------------------------------------
// Launch
// ---------------------------------------------------------------------------
extern "C" void kernel_launch(void* const* d_in, const int* in_sizes, int n_in,
                              void* d_out, int out_size) {
    const float* x     = (const float*)d_in[0];
    const float* gamma = (const float*)d_in[1];
    const float* beta  = (const float*)d_in[2];
    const float* Wqkv  = (const float*)d_in[3];
    const float* Wout  = (const float*)d_in[4];
    const float* bout  = (const float*)d_in[5];
    const float* convw = (const float*)d_in[6];
    float* out = (float*)d_out;

    bf16 *xn, *q, *v, *kT, *ql, *klT, *a1, *a3, *a2;
    bf16 *z, *z2, *xz, *tb, *ub, *av, *zav, *outh;
    void* p;
    cudaGetSymbolAddress(&p, g_xn);   xn   = (bf16*)p;
    cudaGetSymbolAddress(&p, g_q);    q    = (bf16*)p;
    cudaGetSymbolAddress(&p, g_v);    v    = (bf16*)p;
    cudaGetSymbolAddress(&p, g_kT);   kT   = (bf16*)p;
    cudaGetSymbolAddress(&p, g_ql);   ql   = (bf16*)p;
    cudaGetSymbolAddress(&p, g_klT);  klT  = (bf16*)p;
    cudaGetSymbolAddress(&p, g_a1);   a1   = (bf16*)p;
    cudaGetSymbolAddress(&p, g_a3);   a3   = (bf16*)p;
    cudaGetSymbolAddress(&p, g_a2);   a2   = (bf16*)p;
    cudaGetSymbolAddress(&p, g_z);    z    = (bf16*)p;
    cudaGetSymbolAddress(&p, g_z2);   z2   = (bf16*)p;
    cudaGetSymbolAddress(&p, g_xz);   xz   = (bf16*)p;
    cudaGetSymbolAddress(&p, g_t);    tb   = (bf16*)p;
    cudaGetSymbolAddress(&p, g_u);    ub   = (bf16*)p;
    cudaGetSymbolAddress(&p, g_av);   av   = (bf16*)p;
    cudaGetSymbolAddress(&p, g_zav);  zav  = (bf16*)p;
    cudaGetSymbolAddress(&p, g_outh); outh = (bf16*)p;

    const size_t MM  = (size_t)CM * CM;
    const size_t NDH = (size_t)CN * CDH;

    // 1) LayerNorm
    ln_kernel<<<CB * CN, 128>>>(x, gamma, beta);

    // 2) QKV projection fused with head split/scale/transpose (B fp32)
    tc_gemm<128, 128, 1, false, false><<<dim3(CT3 / 128, CB * CN / 128, 1), 256>>>(
        xn, Wqkv, nullptr, CD, CD, CT3, 0, 0, 0, 0, 1.0f, 0.0f, 1.0f, nullptr, nullptr);

    // 3) Landmarks
    landmark_kernel<<<(CBH * CM * CDH) / 256, 256>>>();

    // 4) Similarities
    tc_gemm<128, 128, 0, true, false><<<dim3(CM / 128, CN / 128, CBH), 256>>>(
        q, klT, a1, CDH, CDH, CM, CM,
        NDH, (size_t)CDH * CM, (size_t)CN * CM, 1.0f, 0.0f, 1.0f, nullptr, nullptr);
    tc_gemm<64, 128, 0, true, false><<<dim3(CM / 128, CM / 64, CBH), 256>>>(
        ql, klT, a2, CDH, CDH, CM, CM,
        (size_t)CM * CDH, (size_t)CDH * CM, MM, 1.0f, 0.0f, 1.0f, nullptr, nullptr);
    tc_gemm<128, 128, 0, true, false><<<dim3(CN / 128, CM / 128, CBH), 256>>>(
        ql, kT, a3, CDH, CDH, CN, CN,
        (size_t)CM * CDH, (size_t)CDH * CN, (size_t)CM * CN, 1.0f, 0.0f, 1.0f,
        nullptr, nullptr);

    // 5) Softmaxes
    softmax_rows<1><<<CBH * CN, 256>>>(a1, CM);
    softmax_rows<1><<<CBH * CM, 256>>>(a2, CM);
    softmax_rows<16><<<CBH * CM, 256>>>(a3, CN);

    // 6) Moore-Penrose pinv (6 Newton iterations)
    init_scalars<<<1, 1>>>();
    absmax_sums<<<CBH, 256>>>();
    zinit_kernel<<<(CBH * CM * CM) / 256, 256>>>();
    bf16* zc = z;
    bf16* zn = z2;
    for (int it = 0; it < 6; it++) {
        tc_gemm<64, 128, 0, true, false><<<dim3(2, 4, CBH), 256>>>(
            a2, zc, xz, CM, CM, CM, CM, MM, MM, MM, 1.0f, 0.0f, 1.0f, nullptr, nullptr);
        tc_gemm<64, 128, 0, true, true><<<dim3(2, 4, CBH), 256>>>(
            xz, xz, tb, CM, CM, CM, CM, MM, MM, MM, 1.0f, 7.0f, -1.0f, nullptr, nullptr);
        tc_gemm<64, 128, 0, true, true><<<dim3(2, 4, CBH), 256>>>(
            xz, tb, ub, CM, CM, CM, CM, MM, MM, MM, 1.0f, 15.0f, -1.0f, nullptr, nullptr);
        tc_gemm<64, 128, 0, true, true><<<dim3(2, 4, CBH), 256>>>(
            zc, ub, zn, CM, CM, CM, CM, MM, MM, MM, 0.25f, 13.0f, -1.0f, nullptr, nullptr);
        bf16* tmp = zc; zc = zn; zn = tmp;
    }

    // 7) av = attn3 @ v
    tc_gemm<64, 64, 0, true, false><<<dim3(1, CM / 64, CBH), 256>>>(
        a3, v, av, CN, CN, CDH, CDH,
        (size_t)CM * CN, NDH, (size_t)CM * CDH, 1.0f, 0.0f, 1.0f, nullptr, nullptr);

    // 8) zav = z @ av
    tc_gemm<64, 64, 0, true, false><<<dim3(1, CM / 64, CBH), 256>>>(
        zc, av, zav, CM, CM, CDH, CDH,
        MM, (size_t)CM * CDH, (size_t)CM * CDH, 1.0f, 0.0f, 1.0f, nullptr, nullptr);

    // 9) outh = attn1 @ zav
    tc_gemm<128, 64, 0, true, false><<<dim3(1, CN / 128, CBH), 256>>>(
        a1, zav, outh, CM, CM, CDH, CDH,
        (size_t)CN * CM, (size_t)CM * CDH, NDH, 1.0f, 0.0f, 1.0f, nullptr, nullptr);

    // 10) depthwise conv residual
    conv_res<<<(CBH * CN * CDH) / 1024, 256>>>(convw);

    // 11) final projection + bias + residual (gather-A epilogue)
    tc_gemm<128, 128, 2, false, false><<<dim3(CD / 128, CB * CN / 128, 1), 256>>>(
        outh, Wout, out, CD, 0, CD, CD, 0, 0, 0, 1.0f, 0.0f, 1.0f, x, bout);
}

// round 5
// speedup vs baseline: 4.1423x; 1.2320x over previous
#include <cuda_runtime.h>
#include <cuda_bf16.h>
#include <math.h>
#include <stdint.h>

constexpr int CB  = 4;
constexpr int CN  = 4096;
constexpr int CD  = 512;
constexpr int CH  = 8;
constexpr int CDH = 64;
constexpr int CM  = 256;
constexpr int CL  = 16;
constexpr int CBH = CB * CH;    // 32
constexpr int CT3 = 3 * CD;     // 1536
constexpr float EPS = 1e-5f;

typedef __nv_bfloat16 bf16;
typedef __nv_bfloat162 bf162;

// ---------------------------------------------------------------------------
// Device scratch
// ---------------------------------------------------------------------------
__device__ __align__(16) bf16 g_xn  [(size_t)CB * CN * CD];
__device__ __align__(16) bf16 g_q   [(size_t)CBH * CN * CDH];
__device__ __align__(16) bf16 g_v   [(size_t)CBH * CN * CDH];
__device__ __align__(16) bf16 g_kT  [(size_t)CBH * CDH * CN];
__device__ __align__(16) bf16 g_ql  [(size_t)CBH * CM * CDH];
__device__ __align__(16) bf16 g_klT [(size_t)CBH * CDH * CM];
__device__ __align__(16) bf16 g_a1  [(size_t)CBH * CN * CM];
__device__ __align__(16) bf16 g_a3  [(size_t)CBH * CM * CN];
__device__ __align__(16) bf16 g_a2  [(size_t)CBH * CM * CM];
__device__ __align__(16) bf16 g_z   [(size_t)CBH * CM * CM];
__device__ __align__(16) bf16 g_z2  [(size_t)CBH * CM * CM];
__device__ __align__(16) bf16 g_xz  [(size_t)CBH * CM * CM];
__device__ __align__(16) bf16 g_t   [(size_t)CBH * CM * CM];
__device__ __align__(16) bf16 g_u   [(size_t)CBH * CM * CM];
__device__ __align__(16) bf16 g_av  [(size_t)CBH * CM * CDH];
__device__ __align__(16) bf16 g_zav [(size_t)CBH * CM * CDH];
__device__ __align__(16) bf16 g_outh[(size_t)CBH * CN * CDH];
__device__ __align__(16) bf16 g_wq16[(size_t)CD * CT3];
__device__ __align__(16) bf16 g_wo16[(size_t)CD * CD];
__device__ unsigned g_maxc, g_maxr;

// ---------------------------------------------------------------------------
// helpers
// ---------------------------------------------------------------------------
__device__ __forceinline__ uint32_t pack2(float a, float b) {
    bf162 h = __floats2bfloat162_rn(a, b);
    return *reinterpret_cast<uint32_t*>(&h);
}
__device__ __forceinline__ float2 unpk(uint32_t u) {
    bf162 h = *reinterpret_cast<bf162*>(&u);
    return __bfloat1622float2(h);
}
__device__ __forceinline__ void mma16(float* c, const uint32_t* a,
                                      uint32_t b0, uint32_t b1) {
    asm volatile(
        "mma.sync.aligned.m16n8k16.row.col.f32.bf16.bf16.f32 "
        "{%0,%1,%2,%3},{%4,%5,%6,%7},{%8,%9},{%0,%1,%2,%3};"
        : "+f"(c[0]), "+f"(c[1]), "+f"(c[2]), "+f"(c[3])
        : "r"(a[0]), "r"(a[1]), "r"(a[2]), "r"(a[3]), "r"(b0), "r"(b1));
}
__device__ __forceinline__ void ldsm4(uint32_t* r, uint32_t addr) {
    asm volatile(
        "ldmatrix.sync.aligned.m8n8.x4.shared.b16 {%0,%1,%2,%3},[%4];"
        : "=r"(r[0]), "=r"(r[1]), "=r"(r[2]), "=r"(r[3]) : "r"(addr));
}
__device__ __forceinline__ void ldsm4t(uint32_t& r0, uint32_t& r1,
                                       uint32_t& r2, uint32_t& r3, uint32_t addr) {
    asm volatile(
        "ldmatrix.sync.aligned.m8n8.x4.trans.shared.b16 {%0,%1,%2,%3},[%4];"
        : "=r"(r0), "=r"(r1), "=r"(r2), "=r"(r3) : "r"(addr));
}

// ---------------------------------------------------------------------------
// bf16 tensor-core batched GEMM.  C = alpha * A @ (diagc*I + bsign*B)
// BK=32, 256 threads, warp grid WGM x WGN, warp tile (BM/WGM) x (BN/WGN).
// MODE 0: bf16 store       MODE 1: QKV scatter epilogue
// MODE 2: final (gather A, out = acc + X + bias, fp32)
// MODE 3: fused row-softmax (requires BN == full row width), bf16 store
// ---------------------------------------------------------------------------
template <int BM, int BN, int WGM, int WGN, int MODE, bool DIAG, int MINB>
__global__ __launch_bounds__(256, MINB)
void tc_gemm(const bf16* __restrict__ A, const bf16* __restrict__ B,
             void* __restrict__ Cp,
             int K, int lda, int ldb, int ldc,
             size_t sA, size_t sB, size_t sC,
             float alpha, float diagc, float bsign,
             const float* __restrict__ X, const float* __restrict__ bias) {
    constexpr int WROWS = BM / WGM;
    constexpr int WCOLS = BN / WGN;
    constexpr int MI    = WROWS / 16;
    constexpr int NFR   = WCOLS / 8;
    constexpr int TPRA  = 256 / BM;
    constexpr int KSPAN = 32 / TPRA;
    constexpr int NU4   = KSPAN / 8;
    constexpr int TPRB  = BN / 8;
    constexpr int RPPB  = 256 / TPRB;
    constexpr int BPASS = 32 / RPPB;
    constexpr int AP    = 40;          // A pitch (halves)
    constexpr int BPH   = BN + 8;      // B pitch (halves)

    __shared__ bf16 As[BM * AP];
    __shared__ bf16 Bs[32 * BPH];
    __shared__ float sred[(MODE == 3) ? 2 * BM * WGN : 2];

    const int t = threadIdx.x, warp = t >> 5, lane = t & 31;
    const int wm = warp / WGN, wn = warp % WGN;
    const int g = lane >> 2, tg = lane & 3;
    const int rowBase = blockIdx.y * BM;
    const int colBase = blockIdx.x * BN;
    const int arow = t % BM, akg = (t / BM) * KSPAN;
    const int brow = t / TPRB, bcol = (t % TPRB) * 8;

    const bf16* Ab = A + blockIdx.z * sA;
    const bf16* Bb = B + blockIdx.z * sB;

    const uint32_t asb = (uint32_t)__cvta_generic_to_shared(As);
    const uint32_t bsb = (uint32_t)__cvta_generic_to_shared(Bs);
    const uint32_t aoff = asb +
        ((((lane >> 3) & 1) * 8 + (lane & 7)) * AP + (lane >> 4) * 8) * 2;
    const uint32_t boff = bsb +
        ((((lane >> 3) & 1) * 8 + (lane & 7)) * BPH + wn * WCOLS + (lane >> 4) * 8) * 2;

    uint4 pa[NU4];
    uint4 pbb[BPASS];

    auto ldA = [&](int k0) {
        if (MODE == 2) {
            int r = rowBase + arow;
            int b_ = r >> 12, n = r & (CN - 1);
            int c = k0 + akg;
            int h_ = c >> 6, dh = c & 63;
            const bf16* p = Ab + ((((size_t)(b_ * CH + h_)) * CN + n) * CDH + dh);
#pragma unroll
            for (int i = 0; i < NU4; i++) pa[i] = *(const uint4*)(p + i * 8);
        } else {
            const bf16* p = Ab + (size_t)(rowBase + arow) * lda + k0 + akg;
#pragma unroll
            for (int i = 0; i < NU4; i++) pa[i] = *(const uint4*)(p + i * 8);
        }
    };
    auto ldB = [&](int k0) {
#pragma unroll
        for (int i = 0; i < BPASS; i++)
            pbb[i] = *(const uint4*)(Bb + (size_t)(k0 + brow + i * RPPB) * ldb +
                                     colBase + bcol);
    };
    auto stage = [&](int k0) {
#pragma unroll
        for (int i = 0; i < NU4; i++)
            *(uint4*)&As[arow * AP + akg + i * 8] = pa[i];
#pragma unroll
        for (int i = 0; i < BPASS; i++) {
            int r = brow + i * RPPB;
            uint4 u;
            if (DIAG) {
                float e[8];
                float2 f;
                f = unpk(pbb[i].x); e[0] = f.x; e[1] = f.y;
                f = unpk(pbb[i].y); e[2] = f.x; e[3] = f.y;
                f = unpk(pbb[i].z); e[4] = f.x; e[5] = f.y;
                f = unpk(pbb[i].w); e[6] = f.x; e[7] = f.y;
                int kr = k0 + r;
                int cb = colBase + bcol;
#pragma unroll
                for (int j = 0; j < 8; j++)
                    e[j] = bsign * e[j] + ((kr == cb + j) ? diagc : 0.0f);
                u.x = pack2(e[0], e[1]); u.y = pack2(e[2], e[3]);
                u.z = pack2(e[4], e[5]); u.w = pack2(e[6], e[7]);
            } else {
                u = pbb[i];
            }
            *(uint4*)&Bs[r * BPH + bcol] = u;
        }
    };

    float acc[MI][NFR][4] = {};

    ldA(0); ldB(0); stage(0);
    __syncthreads();
    for (int k0 = 0;; k0 += 32) {
        const int kn = k0 + 32;
        const bool more = kn < K;
        if (more) { ldA(kn); ldB(kn); }
#pragma unroll
        for (int ks = 0; ks < 2; ks++) {
            uint32_t af[MI][4];
#pragma unroll
            for (int mi = 0; mi < MI; mi++)
                ldsm4(af[mi], aoff + ((wm * WROWS + mi * 16) * AP + ks * 16) * 2);
            uint32_t bfr[NFR][2];
#pragma unroll
            for (int np = 0; np < NFR / 2; np++)
                ldsm4t(bfr[2 * np][0], bfr[2 * np][1],
                       bfr[2 * np + 1][0], bfr[2 * np + 1][1],
                       boff + (ks * 16 * BPH + np * 16) * 2);
#pragma unroll
            for (int ni = 0; ni < NFR; ni++)
#pragma unroll
                for (int mi = 0; mi < MI; mi++)
                    mma16(acc[mi][ni], af[mi], bfr[ni][0], bfr[ni][1]);
        }
        if (!more) break;
        __syncthreads();
        stage(kn);
        __syncthreads();
    }

    // ------------------------------ epilogue -------------------------------
    bf16*  Cb16 = (bf16*)Cp + blockIdx.z * sC;
    float* Cbf  = (float*)Cp + blockIdx.z * sC;

    if (MODE == 3) {
        float* smax = sred;
        float* ssum = sred + BM * WGN;
#pragma unroll
        for (int mi = 0; mi < MI; mi++)
#pragma unroll
            for (int h2 = 0; h2 < 2; h2++) {
                float m = -3.4e38f;
#pragma unroll
                for (int ni = 0; ni < NFR; ni++) {
                    m = fmaxf(m, acc[mi][ni][h2 * 2]);
                    m = fmaxf(m, acc[mi][ni][h2 * 2 + 1]);
                }
                m = fmaxf(m, __shfl_xor_sync(0xffffffffu, m, 1));
                m = fmaxf(m, __shfl_xor_sync(0xffffffffu, m, 2));
                int rl = wm * WROWS + mi * 16 + h2 * 8 + g;
                if (tg == 0) smax[rl * WGN + wn] = m;
            }
        __syncthreads();
#pragma unroll
        for (int mi = 0; mi < MI; mi++)
#pragma unroll
            for (int h2 = 0; h2 < 2; h2++) {
                int rl = wm * WROWS + mi * 16 + h2 * 8 + g;
                float tm = smax[rl * WGN];
#pragma unroll
                for (int w = 1; w < WGN; w++) tm = fmaxf(tm, smax[rl * WGN + w]);
                float s = 0.0f;
#pragma unroll
                for (int ni = 0; ni < NFR; ni++) {
                    float e0 = expf(acc[mi][ni][h2 * 2]     - tm);
                    float e1 = expf(acc[mi][ni][h2 * 2 + 1] - tm);
                    acc[mi][ni][h2 * 2]     = e0;
                    acc[mi][ni][h2 * 2 + 1] = e1;
                    s += e0 + e1;
                }
                s += __shfl_xor_sync(0xffffffffu, s, 1);
                s += __shfl_xor_sync(0xffffffffu, s, 2);
                if (tg == 0) ssum[rl * WGN + wn] = s;
            }
        __syncthreads();
#pragma unroll
        for (int mi = 0; mi < MI; mi++)
#pragma unroll
            for (int h2 = 0; h2 < 2; h2++) {
                int rl = wm * WROWS + mi * 16 + h2 * 8 + g;
                float s = 0.0f;
#pragma unroll
                for (int w = 0; w < WGN; w++) s += ssum[rl * WGN + w];
                float inv = 1.0f / s;
                int r = rowBase + rl;
#pragma unroll
                for (int ni = 0; ni < NFR; ni++) {
                    int c0 = colBase + wn * WCOLS + ni * 8 + 2 * tg;
                    *(uint32_t*)&Cb16[(size_t)r * ldc + c0] =
                        pack2(acc[mi][ni][h2 * 2] * inv,
                              acc[mi][ni][h2 * 2 + 1] * inv);
                }
            }
        return;
    }

#pragma unroll
    for (int mi = 0; mi < MI; mi++)
#pragma unroll
        for (int ni = 0; ni < NFR; ni++) {
            int r0 = rowBase + wm * WROWS + mi * 16 + g;
            int c0 = colBase + wn * WCOLS + ni * 8 + 2 * tg;
#pragma unroll
            for (int h2 = 0; h2 < 2; h2++) {
                int r = r0 + h2 * 8;
                float vx = alpha * acc[mi][ni][h2 * 2];
                float vy = alpha * acc[mi][ni][h2 * 2 + 1];
                if (MODE == 0) {
                    *(uint32_t*)&Cb16[(size_t)r * ldc + c0] = pack2(vx, vy);
                } else if (MODE == 1) {
                    int b_ = r >> 12, n = r & (CN - 1);
                    int which = c0 >> 9, inner = c0 & 511;
                    int h_ = inner >> 6, dh = inner & 63;
                    size_t off = (((size_t)(b_ * CH + h_)) * CN + n) * CDH + dh;
                    if (which == 0) {
                        *(uint32_t*)&g_q[off] = pack2(vx * 0.125f, vy * 0.125f);
                    } else if (which == 1) {
                        size_t ot = (((size_t)(b_ * CH + h_)) * CDH + dh) * CN + n;
                        g_kT[ot]      = __float2bfloat16(vx);
                        g_kT[ot + CN] = __float2bfloat16(vy);
                    } else {
                        *(uint32_t*)&g_v[off] = pack2(vx, vy);
                    }
                } else {
                    size_t o = (size_t)r * CD + c0;
                    float2 xr = *(const float2*)&X[o];
                    float2 br = *(const float2*)&bias[c0];
                    *(float2*)&Cbf[o] = make_float2(vx + xr.x + br.x,
                                                    vy + xr.y + br.y);
                }
            }
        }
}

// ---------------------------------------------------------------------------
// Weight conversion fp32 -> bf16 (Wqkv, Wout)
// ---------------------------------------------------------------------------
__global__ void convert_w(const float* __restrict__ Wqkv,
                          const float* __restrict__ Wout) {
    int i = (blockIdx.x * 256 + threadIdx.x) * 4;
    const int n1 = CD * CT3;
    if (i < n1) {
        float4 v = *(const float4*)&Wqkv[i];
        uint2 o; o.x = pack2(v.x, v.y); o.y = pack2(v.z, v.w);
        *(uint2*)&g_wq16[i] = o;
    }
    if (i < CD * CD) {
        float4 v = *(const float4*)&Wout[i];
        uint2 o; o.x = pack2(v.x, v.y); o.y = pack2(v.z, v.w);
        *(uint2*)&g_wo16[i] = o;
    }
}

// ---------------------------------------------------------------------------
// LayerNorm -> bf16
// ---------------------------------------------------------------------------
__global__ void ln_kernel(const float* __restrict__ x,
                          const float* __restrict__ gamma,
                          const float* __restrict__ beta) {
    int row = blockIdx.x;
    int t = threadIdx.x;  // 128
    const float4* xr = (const float4*)(x + (size_t)row * CD);
    float4 v = xr[t];
    float s  = v.x + v.y + v.z + v.w;
    float ss = v.x * v.x + v.y * v.y + v.z * v.z + v.w * v.w;
    __shared__ float shs[4], shss[4];
#pragma unroll
    for (int o = 16; o > 0; o >>= 1) {
        s  += __shfl_down_sync(0xffffffffu, s,  o);
        ss += __shfl_down_sync(0xffffffffu, ss, o);
    }
    int wid = t >> 5, lane = t & 31;
    if (!lane) { shs[wid] = s; shss[wid] = ss; }
    __syncthreads();
    s  = shs[0]  + shs[1]  + shs[2]  + shs[3];
    ss = shss[0] + shss[1] + shss[2] + shss[3];
    float mean = s * (1.0f / CD);
    float var  = ss * (1.0f / CD) - mean * mean;
    float inv  = rsqrtf(var + EPS);
    float4 gg = ((const float4*)gamma)[t];
    float4 bb = ((const float4*)beta)[t];
    uint2 o;
    o.x = pack2((v.x - mean) * inv * gg.x + bb.x, (v.y - mean) * inv * gg.y + bb.y);
    o.y = pack2((v.z - mean) * inv * gg.z + bb.z, (v.w - mean) * inv * gg.w + bb.w);
    *(uint2*)&g_xn[(size_t)row * CD + t * 4] = o;
}

// ---------------------------------------------------------------------------
// Landmark means (q from g_q, k from g_kT)
// ---------------------------------------------------------------------------
__global__ void landmark_kernel() {
    int idx = blockIdx.x * 256 + threadIdx.x;  // BH*M*DH
    int dh = idx & 63;
    int mi = (idx >> 6) & 255;
    int bh = idx >> 14;
    size_t qbase = ((size_t)bh * CN + mi * CL) * CDH + dh;
    float sq = 0.0f;
#pragma unroll
    for (int j = 0; j < CL; j++)
        sq += __bfloat162float(g_q[qbase + (size_t)j * CDH]);
    size_t kbase = ((size_t)bh * CDH + dh) * CN + mi * CL;
    float sk = 0.0f;
#pragma unroll
    for (int j = 0; j < CL; j++)
        sk += __bfloat162float(g_kT[kbase + j]);
    g_ql [((size_t)bh * CM + mi) * CDH + dh] = __float2bfloat16(sq * (1.0f / CL));
    g_klT[((size_t)bh * CDH + dh) * CM + mi] = __float2bfloat16(sk * (1.0f / CL));
}

// ---------------------------------------------------------------------------
// Row softmax for a3 (rows of 4096)
// ---------------------------------------------------------------------------
template <int IT>
__global__ void softmax_rows(bf16* __restrict__ p, int len) {
    bf16* r = p + (size_t)blockIdx.x * len;
    int t = threadIdx.x;
    float vals[IT];
    float mx = -3.4e38f;
#pragma unroll
    for (int i = 0; i < IT; i++) {
        vals[i] = __bfloat162float(r[t + i * 256]);
        mx = fmaxf(mx, vals[i]);
    }
    __shared__ float sh[8];
#pragma unroll
    for (int o = 16; o > 0; o >>= 1) mx = fmaxf(mx, __shfl_xor_sync(0xffffffffu, mx, o));
    int wid = t >> 5, lane = t & 31;
    if (!lane) sh[wid] = mx;
    __syncthreads();
    mx = sh[0];
#pragma unroll
    for (int w = 1; w < 8; w++) mx = fmaxf(mx, sh[w]);
    __syncthreads();
    float s = 0.0f;
#pragma unroll
    for (int i = 0; i < IT; i++) {
        vals[i] = expf(vals[i] - mx);
        s += vals[i];
    }
#pragma unroll
    for (int o = 16; o > 0; o >>= 1) s += __shfl_xor_sync(0xffffffffu, s, o);
    if (!lane) sh[wid] = s;
    __syncthreads();
    s = sh[0];
#pragma unroll
    for (int w = 1; w < 8; w++) s += sh[w];
    float inv = 1.0f / s;
#pragma unroll
    for (int i = 0; i < IT; i++) r[t + i * 256] = __float2bfloat16(vals[i] * inv);
}

// ---------------------------------------------------------------------------
// Pinv init
// ---------------------------------------------------------------------------
__global__ void init_scalars() { g_maxc = 0u; g_maxr = 0u; }

__global__ void absmax_sums() {
    int bh = blockIdx.x;
    int t = threadIdx.x;
    const bf16* a = g_a2 + (size_t)bh * CM * CM;
    float rs = 0.0f, cs = 0.0f;
    for (int j = 0; j < CM; j++) rs += fabsf(__bfloat162float(a[(size_t)t * CM + j]));
    for (int i = 0; i < CM; i++) cs += fabsf(__bfloat162float(a[(size_t)i * CM + t]));
    atomicMax(&g_maxc, __float_as_uint(rs));
    atomicMax(&g_maxr, __float_as_uint(cs));
}

__global__ void zinit_kernel() {
    int idx = blockIdx.x * 256 + threadIdx.x;
    int j = idx & 255;
    int i = (idx >> 8) & 255;
    int bh = idx >> 16;
    float denom = __uint_as_float(g_maxc) * __uint_as_float(g_maxr);
    g_z[((size_t)bh << 16) + (size_t)i * CM + j] =
        __float2bfloat16(__bfloat162float(g_a2[((size_t)bh << 16) + (size_t)j * CM + i]) / denom);
}

// ---------------------------------------------------------------------------
// Depthwise conv residual (sliding window, 4 outputs/thread)
// ---------------------------------------------------------------------------
__global__ void conv_res(const float* __restrict__ w) {
    __shared__ float ws[33];
    int idx = blockIdx.x * 256 + threadIdx.x;
    int dh = idx & 63;
    int nq = (idx >> 6) & 1023;   // CN/4
    int bh = idx >> 16;
    int h_ = bh & 7;
    if (threadIdx.x < 33) ws[threadIdx.x] = w[h_ * 33 + threadIdx.x];
    __syncthreads();
    int n0 = nq * 4;
    size_t base = ((size_t)bh * CN) * CDH + dh;
    float vv[36];
#pragma unroll
    for (int j = 0; j < 36; j++) {
        int nn = n0 - 16 + j;
        vv[j] = (nn >= 0 && nn < CN)
                    ? __bfloat162float(g_v[base + (size_t)nn * CDH]) : 0.0f;
    }
#pragma unroll
    for (int i = 0; i < 4; i++) {
        float s = 0.0f;
#pragma unroll
        for (int k2 = 0; k2 < 33; k2++) s += ws[k2] * vv[k2 + i];
        size_t o = base + (size_t)(n0 + i) * CDH;
        g_outh[o] = __float2bfloat16(__bfloat162float(g_outh[o]) + s);
    }
}

// ---------------------------------------------------------------------------
// Launch
// ---------------------------------------------------------------------------
extern "C" void kernel_launch(void* const* d_in, const int* in_sizes, int n_in,
                              void* d_out, int out_size) {
    const float* x     = (const float*)d_in[0];
    const float* gamma = (const float*)d_in[1];
    const float* beta  = (const float*)d_in[2];
    const float* Wqkv  = (const float*)d_in[3];
    const float* Wout  = (const float*)d_in[4];
    const float* bout  = (const float*)d_in[5];
    const float* convw = (const float*)d_in[6];
    float* out = (float*)d_out;

    bf16 *xn, *q, *v, *kT, *ql, *klT, *a1, *a3, *a2;
    bf16 *z, *z2, *xz, *tb, *ub, *av, *zav, *outh, *wq16, *wo16;
    void* p;
    cudaGetSymbolAddress(&p, g_xn);   xn   = (bf16*)p;
    cudaGetSymbolAddress(&p, g_q);    q    = (bf16*)p;
    cudaGetSymbolAddress(&p, g_v);    v    = (bf16*)p;
    cudaGetSymbolAddress(&p, g_kT);   kT   = (bf16*)p;
    cudaGetSymbolAddress(&p, g_ql);   ql   = (bf16*)p;
    cudaGetSymbolAddress(&p, g_klT);  klT  = (bf16*)p;
    cudaGetSymbolAddress(&p, g_a1);   a1   = (bf16*)p;
    cudaGetSymbolAddress(&p, g_a3);   a3   = (bf16*)p;
    cudaGetSymbolAddress(&p, g_a2);   a2   = (bf16*)p;
    cudaGetSymbolAddress(&p, g_z);    z    = (bf16*)p;
    cudaGetSymbolAddress(&p, g_z2);   z2   = (bf16*)p;
    cudaGetSymbolAddress(&p, g_xz);   xz   = (bf16*)p;
    cudaGetSymbolAddress(&p, g_t);    tb   = (bf16*)p;
    cudaGetSymbolAddress(&p, g_u);    ub   = (bf16*)p;
    cudaGetSymbolAddress(&p, g_av);   av   = (bf16*)p;
    cudaGetSymbolAddress(&p, g_zav);  zav  = (bf16*)p;
    cudaGetSymbolAddress(&p, g_outh); outh = (bf16*)p;
    cudaGetSymbolAddress(&p, g_wq16); wq16 = (bf16*)p;
    cudaGetSymbolAddress(&p, g_wo16); wo16 = (bf16*)p;

    const size_t MM  = (size_t)CM * CM;
    const size_t NDH = (size_t)CN * CDH;

    // 1) LayerNorm + weight conversion
    ln_kernel<<<CB * CN, 128>>>(x, gamma, beta);
    convert_w<<<(CD * CT3) / 1024, 256>>>(Wqkv, Wout);

    // 2) QKV projection fused with head split/scale/transpose
    tc_gemm<128, 256, 2, 4, 1, false, 1><<<dim3(CT3 / 256, CB * CN / 128, 1), 256>>>(
        xn, wq16, nullptr, CD, CD, CT3, 0, 0, 0, 0, 1.0f, 0.0f, 1.0f, nullptr, nullptr);

    // 3) Landmarks
    landmark_kernel<<<(CBH * CM * CDH) / 256, 256>>>();

    // 4) Similarities (a1, a2 with fused softmax; a3 plain + separate softmax)
    tc_gemm<128, 256, 2, 4, 3, false, 1><<<dim3(1, CN / 128, CBH), 256>>>(
        q, klT, a1, CDH, CDH, CM, CM,
        NDH, (size_t)CDH * CM, (size_t)CN * CM, 1.0f, 0.0f, 1.0f, nullptr, nullptr);
    tc_gemm<128, 256, 2, 4, 3, false, 1><<<dim3(1, CM / 128, CBH), 256>>>(
        ql, klT, a2, CDH, CDH, CM, CM,
        (size_t)CM * CDH, (size_t)CDH * CM, MM, 1.0f, 0.0f, 1.0f, nullptr, nullptr);
    tc_gemm<128, 256, 2, 4, 0, false, 1><<<dim3(CN / 256, CM / 128, CBH), 256>>>(
        ql, kT, a3, CDH, CDH, CN, CN,
        (size_t)CM * CDH, (size_t)CDH * CN, (size_t)CM * CN, 1.0f, 0.0f, 1.0f,
        nullptr, nullptr);
    softmax_rows<16><<<CBH * CM, 256>>>(a3, CN);

    // 5) Moore-Penrose pinv (6 Newton iterations)
    init_scalars<<<1, 1>>>();
    absmax_sums<<<CBH, 256>>>();
    zinit_kernel<<<(CBH * CM * CM) / 256, 256>>>();
    bf16* zc = z;
    bf16* zn = z2;
    for (int it = 0; it < 6; it++) {
        tc_gemm<128, 128, 2, 4, 0, false, 2><<<dim3(2, 2, CBH), 256>>>(
            a2, zc, xz, CM, CM, CM, CM, MM, MM, MM, 1.0f, 0.0f, 1.0f, nullptr, nullptr);
        tc_gemm<128, 128, 2, 4, 0, true, 2><<<dim3(2, 2, CBH), 256>>>(
            xz, xz, tb, CM, CM, CM, CM, MM, MM, MM, 1.0f, 7.0f, -1.0f, nullptr, nullptr);
        tc_gemm<128, 128, 2, 4, 0, true, 2><<<dim3(2, 2, CBH), 256>>>(
            xz, tb, ub, CM, CM, CM, CM, MM, MM, MM, 1.0f, 15.0f, -1.0f, nullptr, nullptr);
        tc_gemm<128, 128, 2, 4, 0, true, 2><<<dim3(2, 2, CBH), 256>>>(
            zc, ub, zn, CM, CM, CM, CM, MM, MM, MM, 0.25f, 13.0f, -1.0f, nullptr, nullptr);
        bf16* tmp = zc; zc = zn; zn = tmp;
    }

    // 6) av = attn3 @ v
    tc_gemm<64, 64, 4, 2, 0, false, 2><<<dim3(1, CM / 64, CBH), 256>>>(
        a3, v, av, CN, CN, CDH, CDH,
        (size_t)CM * CN, NDH, (size_t)CM * CDH, 1.0f, 0.0f, 1.0f, nullptr, nullptr);

    // 7) zav = z @ av
    tc_gemm<64, 64, 4, 2, 0, false, 2><<<dim3(1, CM / 64, CBH), 256>>>(
        zc, av, zav, CM, CM, CDH, CDH,
        MM, (size_t)CM * CDH, (size_t)CM * CDH, 1.0f, 0.0f, 1.0f, nullptr, nullptr);

    // 8) outh = attn1 @ zav
    tc_gemm<128, 64, 4, 2, 0, false, 2><<<dim3(1, CN / 128, CBH), 256>>>(
        a1, zav, outh, CM, CM, CDH, CDH,
        (size_t)CN * CM, (size_t)CM * CDH, NDH, 1.0f, 0.0f, 1.0f, nullptr, nullptr);

    // 9) depthwise conv residual
    conv_res<<<(CBH * CN * CDH) / 1024, 256>>>(convw);

    // 10) final projection + bias + residual (gather-A epilogue)
    tc_gemm<128, 256, 2, 4, 2, false, 1><<<dim3(CD / 256, CB * CN / 128, 1), 256>>>(
        outh, wo16, out, CD, 0, CD, CD, 0, 0, 0, 1.0f, 0.0f, 1.0f, x, bout);
}

// round 6
// speedup vs baseline: 4.1503x; 1.0019x over previous
#include <cuda_runtime.h>
#include <cuda_bf16.h>
#include <math.h>
#include <stdint.h>

constexpr int CB  = 4;
constexpr int CN  = 4096;
constexpr int CD  = 512;
constexpr int CH  = 8;
constexpr int CDH = 64;
constexpr int CM  = 256;
constexpr int CL  = 16;
constexpr int CBH = CB * CH;    // 32
constexpr int CT3 = 3 * CD;     // 1536
constexpr float EPS = 1e-5f;

typedef __nv_bfloat16 bf16;
typedef __nv_bfloat162 bf162;

// ---------------------------------------------------------------------------
// Device scratch
// ---------------------------------------------------------------------------
__device__ __align__(16) bf16 g_xn  [(size_t)CB * CN * CD];
__device__ __align__(16) bf16 g_q   [(size_t)CBH * CN * CDH];
__device__ __align__(16) bf16 g_v   [(size_t)CBH * CN * CDH];
__device__ __align__(16) bf16 g_kT  [(size_t)CBH * CDH * CN];
__device__ __align__(16) bf16 g_ql  [(size_t)CBH * CM * CDH];
__device__ __align__(16) bf16 g_klT [(size_t)CBH * CDH * CM];
__device__ __align__(16) bf16 g_a1  [(size_t)CBH * CN * CM];
__device__ __align__(16) bf16 g_a3  [(size_t)CBH * CM * CN];
__device__ __align__(16) bf16 g_a2  [(size_t)CBH * CM * CM];
__device__ __align__(16) bf16 g_z   [(size_t)CBH * CM * CM];
__device__ __align__(16) bf16 g_z2  [(size_t)CBH * CM * CM];
__device__ __align__(16) bf16 g_xz  [(size_t)CBH * CM * CM];
__device__ __align__(16) bf16 g_t   [(size_t)CBH * CM * CM];
__device__ __align__(16) bf16 g_u   [(size_t)CBH * CM * CM];
__device__ __align__(16) bf16 g_av  [(size_t)CBH * CM * CDH];
__device__ __align__(16) bf16 g_zav [(size_t)CBH * CM * CDH];
__device__ __align__(16) bf16 g_outh[(size_t)CBH * CN * CDH];
__device__ __align__(16) bf16 g_wq16[(size_t)CD * CT3];
__device__ __align__(16) bf16 g_wo16[(size_t)CD * CD];
__device__ unsigned g_maxc, g_maxr;

// ---------------------------------------------------------------------------
// helpers
// ---------------------------------------------------------------------------
__device__ __forceinline__ uint32_t pack2(float a, float b) {
    bf162 h = __floats2bfloat162_rn(a, b);
    return *reinterpret_cast<uint32_t*>(&h);
}
__device__ __forceinline__ float2 unpk(uint32_t u) {
    bf162 h = *reinterpret_cast<bf162*>(&u);
    return __bfloat1622float2(h);
}
__device__ __forceinline__ void mma16(float* c, const uint32_t* a,
                                      uint32_t b0, uint32_t b1) {
    asm volatile(
        "mma.sync.aligned.m16n8k16.row.col.f32.bf16.bf16.f32 "
        "{%0,%1,%2,%3},{%4,%5,%6,%7},{%8,%9},{%0,%1,%2,%3};"
        : "+f"(c[0]), "+f"(c[1]), "+f"(c[2]), "+f"(c[3])
        : "r"(a[0]), "r"(a[1]), "r"(a[2]), "r"(a[3]), "r"(b0), "r"(b1));
}
__device__ __forceinline__ void ldsm4(uint32_t* r, uint32_t addr) {
    asm volatile(
        "ldmatrix.sync.aligned.m8n8.x4.shared.b16 {%0,%1,%2,%3},[%4];"
        : "=r"(r[0]), "=r"(r[1]), "=r"(r[2]), "=r"(r[3]) : "r"(addr));
}
__device__ __forceinline__ void ldsm4t(uint32_t& r0, uint32_t& r1,
                                       uint32_t& r2, uint32_t& r3, uint32_t addr) {
    asm volatile(
        "ldmatrix.sync.aligned.m8n8.x4.trans.shared.b16 {%0,%1,%2,%3},[%4];"
        : "=r"(r0), "=r"(r1), "=r"(r2), "=r"(r3) : "r"(addr));
}

// ---------------------------------------------------------------------------
// bf16 tensor-core batched GEMM.  C = alpha * A @ (diagc*I + bsign*B)
// BK=32, 256 threads, warp grid WGM x WGN, warp tile (BM/WGM) x (BN/WGN).
// MODE 0: bf16 store       MODE 1: QKV scatter epilogue
// MODE 2: final (gather A, out = acc + X + bias, fp32)
// MODE 3: fused row-softmax (requires BN == full row width), bf16 store
// ---------------------------------------------------------------------------
template <int BM, int BN, int WGM, int WGN, int MODE, bool DIAG, int MINB>
__global__ __launch_bounds__(256, MINB)
void tc_gemm(const bf16* __restrict__ A, const bf16* __restrict__ B,
             void* __restrict__ Cp,
             int K, int lda, int ldb, int ldc,
             size_t sA, size_t sB, size_t sC,
             float alpha, float diagc, float bsign,
             const float* __restrict__ X, const float* __restrict__ bias) {
    constexpr int WROWS = BM / WGM;
    constexpr int WCOLS = BN / WGN;
    constexpr int MI    = WROWS / 16;
    constexpr int NFR   = WCOLS / 8;
    constexpr int TPRA  = 256 / BM;
    constexpr int KSPAN = 32 / TPRA;
    constexpr int NU4   = KSPAN / 8;
    constexpr int TPRB  = BN / 8;
    constexpr int RPPB  = 256 / TPRB;
    constexpr int BPASS = 32 / RPPB;
    constexpr int AP    = 40;          // A pitch (halves)
    constexpr int BPH   = BN + 8;      // B pitch (halves)

    __shared__ bf16 As[BM * AP];
    __shared__ bf16 Bs[32 * BPH];
    __shared__ float sred[(MODE == 3) ? 2 * BM * WGN : 2];

    const int t = threadIdx.x, warp = t >> 5, lane = t & 31;
    const int wm = warp / WGN, wn = warp % WGN;
    const int g = lane >> 2, tg = lane & 3;
    const int rowBase = blockIdx.y * BM;
    const int colBase = blockIdx.x * BN;
    const int arow = t % BM, akg = (t / BM) * KSPAN;
    const int brow = t / TPRB, bcol = (t % TPRB) * 8;

    const bf16* Ab = A + blockIdx.z * sA;
    const bf16* Bb = B + blockIdx.z * sB;

    const uint32_t asb = (uint32_t)__cvta_generic_to_shared(As);
    const uint32_t bsb = (uint32_t)__cvta_generic_to_shared(Bs);
    const uint32_t aoff = asb +
        ((((lane >> 3) & 1) * 8 + (lane & 7)) * AP + (lane >> 4) * 8) * 2;
    const uint32_t boff = bsb +
        ((((lane >> 3) & 1) * 8 + (lane & 7)) * BPH + wn * WCOLS + (lane >> 4) * 8) * 2;

    uint4 pa[NU4];
    uint4 pbb[BPASS];

    auto ldA = [&](int k0) {
        if (MODE == 2) {
            int r = rowBase + arow;
            int b_ = r >> 12, n = r & (CN - 1);
            int c = k0 + akg;
            int h_ = c >> 6, dh = c & 63;
            const bf16* p = Ab + ((((size_t)(b_ * CH + h_)) * CN + n) * CDH + dh);
#pragma unroll
            for (int i = 0; i < NU4; i++) pa[i] = *(const uint4*)(p + i * 8);
        } else {
            const bf16* p = Ab + (size_t)(rowBase + arow) * lda + k0 + akg;
#pragma unroll
            for (int i = 0; i < NU4; i++) pa[i] = *(const uint4*)(p + i * 8);
        }
    };
    auto ldB = [&](int k0) {
#pragma unroll
        for (int i = 0; i < BPASS; i++)
            pbb[i] = *(const uint4*)(Bb + (size_t)(k0 + brow + i * RPPB) * ldb +
                                     colBase + bcol);
    };
    auto stage = [&](int k0) {
#pragma unroll
        for (int i = 0; i < NU4; i++)
            *(uint4*)&As[arow * AP + akg + i * 8] = pa[i];
#pragma unroll
        for (int i = 0; i < BPASS; i++) {
            int r = brow + i * RPPB;
            uint4 u;
            if (DIAG) {
                float e[8];
                float2 f;
                f = unpk(pbb[i].x); e[0] = f.x; e[1] = f.y;
                f = unpk(pbb[i].y); e[2] = f.x; e[3] = f.y;
                f = unpk(pbb[i].z); e[4] = f.x; e[5] = f.y;
                f = unpk(pbb[i].w); e[6] = f.x; e[7] = f.y;
                int kr = k0 + r;
                int cb = colBase + bcol;
#pragma unroll
                for (int j = 0; j < 8; j++)
                    e[j] = bsign * e[j] + ((kr == cb + j) ? diagc : 0.0f);
                u.x = pack2(e[0], e[1]); u.y = pack2(e[2], e[3]);
                u.z = pack2(e[4], e[5]); u.w = pack2(e[6], e[7]);
            } else {
                u = pbb[i];
            }
            *(uint4*)&Bs[r * BPH + bcol] = u;
        }
    };

    float acc[MI][NFR][4] = {};

    ldA(0); ldB(0); stage(0);
    __syncthreads();
    for (int k0 = 0;; k0 += 32) {
        const int kn = k0 + 32;
        const bool more = kn < K;
        if (more) { ldA(kn); ldB(kn); }
#pragma unroll
        for (int ks = 0; ks < 2; ks++) {
            uint32_t af[MI][4];
#pragma unroll
            for (int mi = 0; mi < MI; mi++)
                ldsm4(af[mi], aoff + ((wm * WROWS + mi * 16) * AP + ks * 16) * 2);
            uint32_t bfr[NFR][2];
#pragma unroll
            for (int np = 0; np < NFR / 2; np++)
                ldsm4t(bfr[2 * np][0], bfr[2 * np][1],
                       bfr[2 * np + 1][0], bfr[2 * np + 1][1],
                       boff + (ks * 16 * BPH + np * 16) * 2);
#pragma unroll
            for (int ni = 0; ni < NFR; ni++)
#pragma unroll
                for (int mi = 0; mi < MI; mi++)
                    mma16(acc[mi][ni], af[mi], bfr[ni][0], bfr[ni][1]);
        }
        if (!more) break;
        __syncthreads();
        stage(kn);
        __syncthreads();
    }

    // ------------------------------ epilogue -------------------------------
    bf16*  Cb16 = (bf16*)Cp + blockIdx.z * sC;
    float* Cbf  = (float*)Cp + blockIdx.z * sC;

    if (MODE == 3) {
        float* smax = sred;
        float* ssum = sred + BM * WGN;
#pragma unroll
        for (int mi = 0; mi < MI; mi++)
#pragma unroll
            for (int h2 = 0; h2 < 2; h2++) {
                float m = -3.4e38f;
#pragma unroll
                for (int ni = 0; ni < NFR; ni++) {
                    m = fmaxf(m, acc[mi][ni][h2 * 2]);
                    m = fmaxf(m, acc[mi][ni][h2 * 2 + 1]);
                }
                m = fmaxf(m, __shfl_xor_sync(0xffffffffu, m, 1));
                m = fmaxf(m, __shfl_xor_sync(0xffffffffu, m, 2));
                int rl = wm * WROWS + mi * 16 + h2 * 8 + g;
                if (tg == 0) smax[rl * WGN + wn] = m;
            }
        __syncthreads();
#pragma unroll
        for (int mi = 0; mi < MI; mi++)
#pragma unroll
            for (int h2 = 0; h2 < 2; h2++) {
                int rl = wm * WROWS + mi * 16 + h2 * 8 + g;
                float tm = smax[rl * WGN];
#pragma unroll
                for (int w = 1; w < WGN; w++) tm = fmaxf(tm, smax[rl * WGN + w]);
                float s = 0.0f;
#pragma unroll
                for (int ni = 0; ni < NFR; ni++) {
                    float e0 = expf(acc[mi][ni][h2 * 2]     - tm);
                    float e1 = expf(acc[mi][ni][h2 * 2 + 1] - tm);
                    acc[mi][ni][h2 * 2]     = e0;
                    acc[mi][ni][h2 * 2 + 1] = e1;
                    s += e0 + e1;
                }
                s += __shfl_xor_sync(0xffffffffu, s, 1);
                s += __shfl_xor_sync(0xffffffffu, s, 2);
                if (tg == 0) ssum[rl * WGN + wn] = s;
            }
        __syncthreads();
#pragma unroll
        for (int mi = 0; mi < MI; mi++)
#pragma unroll
            for (int h2 = 0; h2 < 2; h2++) {
                int rl = wm * WROWS + mi * 16 + h2 * 8 + g;
                float s = 0.0f;
#pragma unroll
                for (int w = 0; w < WGN; w++) s += ssum[rl * WGN + w];
                float inv = 1.0f / s;
                int r = rowBase + rl;
#pragma unroll
                for (int ni = 0; ni < NFR; ni++) {
                    int c0 = colBase + wn * WCOLS + ni * 8 + 2 * tg;
                    *(uint32_t*)&Cb16[(size_t)r * ldc + c0] =
                        pack2(acc[mi][ni][h2 * 2] * inv,
                              acc[mi][ni][h2 * 2 + 1] * inv);
                }
            }
        return;
    }

#pragma unroll
    for (int mi = 0; mi < MI; mi++)
#pragma unroll
        for (int ni = 0; ni < NFR; ni++) {
            int r0 = rowBase + wm * WROWS + mi * 16 + g;
            int c0 = colBase + wn * WCOLS + ni * 8 + 2 * tg;
#pragma unroll
            for (int h2 = 0; h2 < 2; h2++) {
                int r = r0 + h2 * 8;
                float vx = alpha * acc[mi][ni][h2 * 2];
                float vy = alpha * acc[mi][ni][h2 * 2 + 1];
                if (MODE == 0) {
                    *(uint32_t*)&Cb16[(size_t)r * ldc + c0] = pack2(vx, vy);
                } else if (MODE == 1) {
                    int b_ = r >> 12, n = r & (CN - 1);
                    int which = c0 >> 9, inner = c0 & 511;
                    int h_ = inner >> 6, dh = inner & 63;
                    size_t off = (((size_t)(b_ * CH + h_)) * CN + n) * CDH + dh;
                    if (which == 0) {
                        *(uint32_t*)&g_q[off] = pack2(vx * 0.125f, vy * 0.125f);
                    } else if (which == 1) {
                        size_t ot = (((size_t)(b_ * CH + h_)) * CDH + dh) * CN + n;
                        g_kT[ot]      = __float2bfloat16(vx);
                        g_kT[ot + CN] = __float2bfloat16(vy);
                    } else {
                        *(uint32_t*)&g_v[off] = pack2(vx, vy);
                    }
                } else {
                    size_t o = (size_t)r * CD + c0;
                    float2 xr = *(const float2*)&X[o];
                    float2 br = *(const float2*)&bias[c0];
                    *(float2*)&Cbf[o] = make_float2(vx + xr.x + br.x,
                                                    vy + xr.y + br.y);
                }
            }
        }
}

// ---------------------------------------------------------------------------
// Weight conversion fp32 -> bf16 (Wqkv, Wout)
// ---------------------------------------------------------------------------
__global__ void convert_w(const float* __restrict__ Wqkv,
                          const float* __restrict__ Wout) {
    int i = (blockIdx.x * 256 + threadIdx.x) * 4;
    const int n1 = CD * CT3;
    if (i < n1) {
        float4 v = *(const float4*)&Wqkv[i];
        uint2 o; o.x = pack2(v.x, v.y); o.y = pack2(v.z, v.w);
        *(uint2*)&g_wq16[i] = o;
    }
    if (i < CD * CD) {
        float4 v = *(const float4*)&Wout[i];
        uint2 o; o.x = pack2(v.x, v.y); o.y = pack2(v.z, v.w);
        *(uint2*)&g_wo16[i] = o;
    }
}

// ---------------------------------------------------------------------------
// LayerNorm -> bf16
// ---------------------------------------------------------------------------
__global__ void ln_kernel(const float* __restrict__ x,
                          const float* __restrict__ gamma,
                          const float* __restrict__ beta) {
    int row = blockIdx.x;
    int t = threadIdx.x;  // 128
    const float4* xr = (const float4*)(x + (size_t)row * CD);
    float4 v = xr[t];
    float s  = v.x + v.y + v.z + v.w;
    float ss = v.x * v.x + v.y * v.y + v.z * v.z + v.w * v.w;
    __shared__ float shs[4], shss[4];
#pragma unroll
    for (int o = 16; o > 0; o >>= 1) {
        s  += __shfl_down_sync(0xffffffffu, s,  o);
        ss += __shfl_down_sync(0xffffffffu, ss, o);
    }
    int wid = t >> 5, lane = t & 31;
    if (!lane) { shs[wid] = s; shss[wid] = ss; }
    __syncthreads();
    s  = shs[0]  + shs[1]  + shs[2]  + shs[3];
    ss = shss[0] + shss[1] + shss[2] + shss[3];
    float mean = s * (1.0f / CD);
    float var  = ss * (1.0f / CD) - mean * mean;
    float inv  = rsqrtf(var + EPS);
    float4 gg = ((const float4*)gamma)[t];
    float4 bb = ((const float4*)beta)[t];
    uint2 o;
    o.x = pack2((v.x - mean) * inv * gg.x + bb.x, (v.y - mean) * inv * gg.y + bb.y);
    o.y = pack2((v.z - mean) * inv * gg.z + bb.z, (v.w - mean) * inv * gg.w + bb.w);
    *(uint2*)&g_xn[(size_t)row * CD + t * 4] = o;
}

// ---------------------------------------------------------------------------
// Landmark means (q from g_q, k from g_kT)
// ---------------------------------------------------------------------------
__global__ void landmark_kernel() {
    int idx = blockIdx.x * 256 + threadIdx.x;  // BH*M*DH
    int dh = idx & 63;
    int mi = (idx >> 6) & 255;
    int bh = idx >> 14;
    size_t qbase = ((size_t)bh * CN + mi * CL) * CDH + dh;
    float sq = 0.0f;
#pragma unroll
    for (int j = 0; j < CL; j++)
        sq += __bfloat162float(g_q[qbase + (size_t)j * CDH]);
    size_t kbase = ((size_t)bh * CDH + dh) * CN + mi * CL;
    float sk = 0.0f;
#pragma unroll
    for (int j = 0; j < CL; j++)
        sk += __bfloat162float(g_kT[kbase + j]);
    g_ql [((size_t)bh * CM + mi) * CDH + dh] = __float2bfloat16(sq * (1.0f / CL));
    g_klT[((size_t)bh * CDH + dh) * CM + mi] = __float2bfloat16(sk * (1.0f / CL));
}

// ---------------------------------------------------------------------------
// Row softmax for a3 (rows of 4096)
// ---------------------------------------------------------------------------
template <int IT>
__global__ void softmax_rows(bf16* __restrict__ p, int len) {
    bf16* r = p + (size_t)blockIdx.x * len;
    int t = threadIdx.x;
    float vals[IT];
    float mx = -3.4e38f;
#pragma unroll
    for (int i = 0; i < IT; i++) {
        vals[i] = __bfloat162float(r[t + i * 256]);
        mx = fmaxf(mx, vals[i]);
    }
    __shared__ float sh[8];
#pragma unroll
    for (int o = 16; o > 0; o >>= 1) mx = fmaxf(mx, __shfl_xor_sync(0xffffffffu, mx, o));
    int wid = t >> 5, lane = t & 31;
    if (!lane) sh[wid] = mx;
    __syncthreads();
    mx = sh[0];
#pragma unroll
    for (int w = 1; w < 8; w++) mx = fmaxf(mx, sh[w]);
    __syncthreads();
    float s = 0.0f;
#pragma unroll
    for (int i = 0; i < IT; i++) {
        vals[i] = expf(vals[i] - mx);
        s += vals[i];
    }
#pragma unroll
    for (int o = 16; o > 0; o >>= 1) s += __shfl_xor_sync(0xffffffffu, s, o);
    if (!lane) sh[wid] = s;
    __syncthreads();
    s = sh[0];
#pragma unroll
    for (int w = 1; w < 8; w++) s += sh[w];
    float inv = 1.0f / s;
#pragma unroll
    for (int i = 0; i < IT; i++) r[t + i * 256] = __float2bfloat16(vals[i] * inv);
}

// ---------------------------------------------------------------------------
// Pinv init
// ---------------------------------------------------------------------------
__global__ void init_scalars() { g_maxc = 0u; g_maxr = 0u; }

__global__ void absmax_sums() {
    int bh = blockIdx.x;
    int t = threadIdx.x;
    const bf16* a = g_a2 + (size_t)bh * CM * CM;
    float rs = 0.0f, cs = 0.0f;
    for (int j = 0; j < CM; j++) rs += fabsf(__bfloat162float(a[(size_t)t * CM + j]));
    for (int i = 0; i < CM; i++) cs += fabsf(__bfloat162float(a[(size_t)i * CM + t]));
    atomicMax(&g_maxc, __float_as_uint(rs));
    atomicMax(&g_maxr, __float_as_uint(cs));
}

__global__ void zinit_kernel() {
    int idx = blockIdx.x * 256 + threadIdx.x;
    int j = idx & 255;
    int i = (idx >> 8) & 255;
    int bh = idx >> 16;
    float denom = __uint_as_float(g_maxc) * __uint_as_float(g_maxr);
    g_z[((size_t)bh << 16) + (size_t)i * CM + j] =
        __float2bfloat16(__bfloat162float(g_a2[((size_t)bh << 16) + (size_t)j * CM + i]) / denom);
}

// ---------------------------------------------------------------------------
// Depthwise conv residual (sliding window, 4 outputs/thread)
// ---------------------------------------------------------------------------
__global__ void conv_res(const float* __restrict__ w) {
    __shared__ float ws[33];
    int idx = blockIdx.x * 256 + threadIdx.x;
    int dh = idx & 63;
    int nq = (idx >> 6) & 1023;   // CN/4
    int bh = idx >> 16;
    int h_ = bh & 7;
    if (threadIdx.x < 33) ws[threadIdx.x] = w[h_ * 33 + threadIdx.x];
    __syncthreads();
    int n0 = nq * 4;
    size_t base = ((size_t)bh * CN) * CDH + dh;
    float vv[36];
#pragma unroll
    for (int j = 0; j < 36; j++) {
        int nn = n0 - 16 + j;
        vv[j] = (nn >= 0 && nn < CN)
                    ? __bfloat162float(g_v[base + (size_t)nn * CDH]) : 0.0f;
    }
#pragma unroll
    for (int i = 0; i < 4; i++) {
        float s = 0.0f;
#pragma unroll
        for (int k2 = 0; k2 < 33; k2++) s += ws[k2] * vv[k2 + i];
        size_t o = base + (size_t)(n0 + i) * CDH;
        g_outh[o] = __float2bfloat16(__bfloat162float(g_outh[o]) + s);
    }
}

// ---------------------------------------------------------------------------
// Launch
// ---------------------------------------------------------------------------
extern "C" void kernel_launch(void* const* d_in, const int* in_sizes, int n_in,
                              void* d_out, int out_size) {
    const float* x     = (const float*)d_in[0];
    const float* gamma = (const float*)d_in[1];
    const float* beta  = (const float*)d_in[2];
    const float* Wqkv  = (const float*)d_in[3];
    const float* Wout  = (const float*)d_in[4];
    const float* bout  = (const float*)d_in[5];
    const float* convw = (const float*)d_in[6];
    float* out = (float*)d_out;

    bf16 *xn, *q, *v, *kT, *ql, *klT, *a1, *a3, *a2;
    bf16 *z, *z2, *xz, *tb, *ub, *av, *zav, *outh, *wq16, *wo16;
    void* p;
    cudaGetSymbolAddress(&p, g_xn);   xn   = (bf16*)p;
    cudaGetSymbolAddress(&p, g_q);    q    = (bf16*)p;
    cudaGetSymbolAddress(&p, g_v);    v    = (bf16*)p;
    cudaGetSymbolAddress(&p, g_kT);   kT   = (bf16*)p;
    cudaGetSymbolAddress(&p, g_ql);   ql   = (bf16*)p;
    cudaGetSymbolAddress(&p, g_klT);  klT  = (bf16*)p;
    cudaGetSymbolAddress(&p, g_a1);   a1   = (bf16*)p;
    cudaGetSymbolAddress(&p, g_a3);   a3   = (bf16*)p;
    cudaGetSymbolAddress(&p, g_a2);   a2   = (bf16*)p;
    cudaGetSymbolAddress(&p, g_z);    z    = (bf16*)p;
    cudaGetSymbolAddress(&p, g_z2);   z2   = (bf16*)p;
    cudaGetSymbolAddress(&p, g_xz);   xz   = (bf16*)p;
    cudaGetSymbolAddress(&p, g_t);    tb   = (bf16*)p;
    cudaGetSymbolAddress(&p, g_u);    ub   = (bf16*)p;
    cudaGetSymbolAddress(&p, g_av);   av   = (bf16*)p;
    cudaGetSymbolAddress(&p, g_zav);  zav  = (bf16*)p;
    cudaGetSymbolAddress(&p, g_outh); outh = (bf16*)p;
    cudaGetSymbolAddress(&p, g_wq16); wq16 = (bf16*)p;
    cudaGetSymbolAddress(&p, g_wo16); wo16 = (bf16*)p;

    const size_t MM  = (size_t)CM * CM;
    const size_t NDH = (size_t)CN * CDH;

    // 1) LayerNorm + weight conversion
    ln_kernel<<<CB * CN, 128>>>(x, gamma, beta);
    convert_w<<<(CD * CT3) / 1024, 256>>>(Wqkv, Wout);

    // 2) QKV projection fused with head split/scale/transpose
    tc_gemm<128, 256, 2, 4, 1, false, 1><<<dim3(CT3 / 256, CB * CN / 128, 1), 256>>>(
        xn, wq16, nullptr, CD, CD, CT3, 0, 0, 0, 0, 1.0f, 0.0f, 1.0f, nullptr, nullptr);

    // 3) Landmarks
    landmark_kernel<<<(CBH * CM * CDH) / 256, 256>>>();

    // 4) Similarities (a1, a2 with fused softmax; a3 plain + separate softmax)
    tc_gemm<128, 256, 2, 4, 3, false, 1><<<dim3(1, CN / 128, CBH), 256>>>(
        q, klT, a1, CDH, CDH, CM, CM,
        NDH, (size_t)CDH * CM, (size_t)CN * CM, 1.0f, 0.0f, 1.0f, nullptr, nullptr);
    tc_gemm<128, 256, 2, 4, 3, false, 1><<<dim3(1, CM / 128, CBH), 256>>>(
        ql, klT, a2, CDH, CDH, CM, CM,
        (size_t)CM * CDH, (size_t)CDH * CM, MM, 1.0f, 0.0f, 1.0f, nullptr, nullptr);
    tc_gemm<128, 256, 2, 4, 0, false, 1><<<dim3(CN / 256, CM / 128, CBH), 256>>>(
        ql, kT, a3, CDH, CDH, CN, CN,
        (size_t)CM * CDH, (size_t)CDH * CN, (size_t)CM * CN, 1.0f, 0.0f, 1.0f,
        nullptr, nullptr);
    softmax_rows<16><<<CBH * CM, 256>>>(a3, CN);

    // 5) Moore-Penrose pinv (6 Newton iterations)
    init_scalars<<<1, 1>>>();
    absmax_sums<<<CBH, 256>>>();
    zinit_kernel<<<(CBH * CM * CM) / 256, 256>>>();
    bf16* zc = z;
    bf16* zn = z2;
    for (int it = 0; it < 6; it++) {
        tc_gemm<128, 128, 2, 4, 0, false, 2><<<dim3(2, 2, CBH), 256>>>(
            a2, zc, xz, CM, CM, CM, CM, MM, MM, MM, 1.0f, 0.0f, 1.0f, nullptr, nullptr);
        tc_gemm<128, 128, 2, 4, 0, true, 2><<<dim3(2, 2, CBH), 256>>>(
            xz, xz, tb, CM, CM, CM, CM, MM, MM, MM, 1.0f, 7.0f, -1.0f, nullptr, nullptr);
        tc_gemm<128, 128, 2, 4, 0, true, 2><<<dim3(2, 2, CBH), 256>>>(
            xz, tb, ub, CM, CM, CM, CM, MM, MM, MM, 1.0f, 15.0f, -1.0f, nullptr, nullptr);
        tc_gemm<128, 128, 2, 4, 0, true, 2><<<dim3(2, 2, CBH), 256>>>(
            zc, ub, zn, CM, CM, CM, CM, MM, MM, MM, 0.25f, 13.0f, -1.0f, nullptr, nullptr);
        bf16* tmp = zc; zc = zn; zn = tmp;
    }

    // 6) av = attn3 @ v
    tc_gemm<64, 64, 4, 2, 0, false, 2><<<dim3(1, CM / 64, CBH), 256>>>(
        a3, v, av, CN, CN, CDH, CDH,
        (size_t)CM * CN, NDH, (size_t)CM * CDH, 1.0f, 0.0f, 1.0f, nullptr, nullptr);

    // 7) zav = z @ av
    tc_gemm<64, 64, 4, 2, 0, false, 2><<<dim3(1, CM / 64, CBH), 256>>>(
        zc, av, zav, CM, CM, CDH, CDH,
        MM, (size_t)CM * CDH, (size_t)CM * CDH, 1.0f, 0.0f, 1.0f, nullptr, nullptr);

    // 8) outh = attn1 @ zav
    tc_gemm<128, 64, 4, 2, 0, false, 2><<<dim3(1, CN / 128, CBH), 256>>>(
        a1, zav, outh, CM, CM, CDH, CDH,
        (size_t)CN * CM, (size_t)CM * CDH, NDH, 1.0f, 0.0f, 1.0f, nullptr, nullptr);

    // 9) depthwise conv residual
    conv_res<<<(CBH * CN * CDH) / 1024, 256>>>(convw);

    // 10) final projection + bias + residual (gather-A epilogue)
    tc_gemm<128, 256, 2, 4, 2, false, 1><<<dim3(CD / 256, CB * CN / 128, 1), 256>>>(
        outh, wo16, out, CD, 0, CD, CD, 0, 0, 0, 1.0f, 0.0f, 1.0f, x, bout);
}

// round 8
// speedup vs baseline: 4.5789x; 1.1033x over previous
#include <cuda_runtime.h>
#include <cuda_bf16.h>
#include <math.h>
#include <stdint.h>

constexpr int CB  = 4;
constexpr int CN  = 4096;
constexpr int CD  = 512;
constexpr int CH  = 8;
constexpr int CDH = 64;
constexpr int CM  = 256;
constexpr int CL  = 16;
constexpr int CBH = CB * CH;    // 32
constexpr int CT3 = 3 * CD;     // 1536
constexpr float EPS = 1e-5f;

typedef __nv_bfloat16 bf16;
typedef __nv_bfloat162 bf162;

// ---------------------------------------------------------------------------
// Device scratch
// ---------------------------------------------------------------------------
__device__ __align__(16) bf16 g_xn  [(size_t)CB * CN * CD];
__device__ __align__(16) bf16 g_q   [(size_t)CBH * CN * CDH];
__device__ __align__(16) bf16 g_v   [(size_t)CBH * CN * CDH];
__device__ __align__(16) bf16 g_kT  [(size_t)CBH * CDH * CN];
__device__ __align__(16) bf16 g_ql  [(size_t)CBH * CM * CDH];
__device__ __align__(16) bf16 g_klT [(size_t)CBH * CDH * CM];
__device__ __align__(16) bf16 g_a1  [(size_t)CBH * CN * CM];
__device__ __align__(16) bf16 g_a3  [(size_t)CBH * CM * CN];
__device__ __align__(16) bf16 g_a2  [(size_t)CBH * CM * CM];
__device__ __align__(16) bf16 g_z   [(size_t)CBH * CM * CM];
__device__ __align__(16) bf16 g_z2  [(size_t)CBH * CM * CM];
__device__ __align__(16) bf16 g_xz  [(size_t)CBH * CM * CM];
__device__ __align__(16) bf16 g_t   [(size_t)CBH * CM * CM];
__device__ __align__(16) bf16 g_u   [(size_t)CBH * CM * CM];
__device__ __align__(16) bf16 g_av  [(size_t)CBH * CM * CDH];
__device__ __align__(16) bf16 g_zav [(size_t)CBH * CM * CDH];
__device__ __align__(16) bf16 g_outh[(size_t)CBH * CN * CDH];
__device__ __align__(16) bf16 g_wq16[(size_t)CD * CT3];
__device__ __align__(16) bf16 g_wo16[(size_t)CD * CD];
__device__ unsigned g_maxc, g_maxr;

// ---------------------------------------------------------------------------
// Fork/join resources (created once at static init; host-side only, no device
// memory; kernel_launch behaves identically on every call)
// ---------------------------------------------------------------------------
struct AuxStreams {
    cudaStream_t s1;
    cudaEvent_t evF, evJ;
    AuxStreams() {
        cudaStreamCreateWithFlags(&s1, cudaStreamNonBlocking);
        cudaEventCreateWithFlags(&evF, cudaEventDisableTiming);
        cudaEventCreateWithFlags(&evJ, cudaEventDisableTiming);
    }
};
static AuxStreams g_aux;

// ---------------------------------------------------------------------------
// helpers
// ---------------------------------------------------------------------------
__device__ __forceinline__ uint32_t pack2(float a, float b) {
    bf162 h = __floats2bfloat162_rn(a, b);
    return *reinterpret_cast<uint32_t*>(&h);
}
__device__ __forceinline__ float2 unpk(uint32_t u) {
    bf162 h = *reinterpret_cast<bf162*>(&u);
    return __bfloat1622float2(h);
}
__device__ __forceinline__ void mma16(float* c, const uint32_t* a,
                                      uint32_t b0, uint32_t b1) {
    asm volatile(
        "mma.sync.aligned.m16n8k16.row.col.f32.bf16.bf16.f32 "
        "{%0,%1,%2,%3},{%4,%5,%6,%7},{%8,%9},{%0,%1,%2,%3};"
        : "+f"(c[0]), "+f"(c[1]), "+f"(c[2]), "+f"(c[3])
        : "r"(a[0]), "r"(a[1]), "r"(a[2]), "r"(a[3]), "r"(b0), "r"(b1));
}
__device__ __forceinline__ void ldsm4(uint32_t* r, uint32_t addr) {
    asm volatile(
        "ldmatrix.sync.aligned.m8n8.x4.shared.b16 {%0,%1,%2,%3},[%4];"
        : "=r"(r[0]), "=r"(r[1]), "=r"(r[2]), "=r"(r[3]) : "r"(addr));
}
__device__ __forceinline__ void ldsm4t(uint32_t& r0, uint32_t& r1,
                                       uint32_t& r2, uint32_t& r3, uint32_t addr) {
    asm volatile(
        "ldmatrix.sync.aligned.m8n8.x4.trans.shared.b16 {%0,%1,%2,%3},[%4];"
        : "=r"(r0), "=r"(r1), "=r"(r2), "=r"(r3) : "r"(addr));
}

// ---------------------------------------------------------------------------
// bf16 tensor-core batched GEMM.  C = alpha * A @ (diagc*I + bsign*B)
// BK=32, 256 threads, warp grid WGM x WGN, warp tile (BM/WGM) x (BN/WGN).
// MODE 0: bf16 store       MODE 1: QKV scatter epilogue
// MODE 2: final (gather A, out = acc + X + bias, fp32)
// MODE 3: fused row-softmax (requires BN == full row width), bf16 store
// MODE 4: bf16 accumulate store (C += acc)
// ---------------------------------------------------------------------------
template <int BM, int BN, int WGM, int WGN, int MODE, bool DIAG, int MINB>
__global__ __launch_bounds__(256, MINB)
void tc_gemm(const bf16* __restrict__ A, const bf16* __restrict__ B,
             void* __restrict__ Cp,
             int K, int lda, int ldb, int ldc,
             size_t sA, size_t sB, size_t sC,
             float alpha, float diagc, float bsign,
             const float* __restrict__ X, const float* __restrict__ bias) {
    constexpr int WROWS = BM / WGM;
    constexpr int WCOLS = BN / WGN;
    constexpr int MI    = WROWS / 16;
    constexpr int NFR   = WCOLS / 8;
    constexpr int TPRA  = 256 / BM;
    constexpr int KSPAN = 32 / TPRA;
    constexpr int NU4   = KSPAN / 8;
    constexpr int TPRB  = BN / 8;
    constexpr int RPPB  = 256 / TPRB;
    constexpr int BPASS = 32 / RPPB;
    constexpr int AP    = 40;
    constexpr int BPH   = BN + 8;

    __shared__ bf16 As[BM * AP];
    __shared__ bf16 Bs[32 * BPH];
    __shared__ float sred[(MODE == 3) ? 2 * BM * WGN : 2];

    const int t = threadIdx.x, warp = t >> 5, lane = t & 31;
    const int wm = warp / WGN, wn = warp % WGN;
    const int g = lane >> 2, tg = lane & 3;
    const int rowBase = blockIdx.y * BM;
    const int colBase = blockIdx.x * BN;
    const int arow = t % BM, akg = (t / BM) * KSPAN;
    const int brow = t / TPRB, bcol = (t % TPRB) * 8;

    const bf16* Ab = A + blockIdx.z * sA;
    const bf16* Bb = B + blockIdx.z * sB;

    const uint32_t asb = (uint32_t)__cvta_generic_to_shared(As);
    const uint32_t bsb = (uint32_t)__cvta_generic_to_shared(Bs);
    const uint32_t aoff = asb +
        ((((lane >> 3) & 1) * 8 + (lane & 7)) * AP + (lane >> 4) * 8) * 2;
    const uint32_t boff = bsb +
        ((((lane >> 3) & 1) * 8 + (lane & 7)) * BPH + wn * WCOLS + (lane >> 4) * 8) * 2;

    uint4 pa[NU4];
    uint4 pbb[BPASS];

    auto ldA = [&](int k0) {
        if (MODE == 2) {
            int r = rowBase + arow;
            int b_ = r >> 12, n = r & (CN - 1);
            int c = k0 + akg;
            int h_ = c >> 6, dh = c & 63;
            const bf16* p = Ab + ((((size_t)(b_ * CH + h_)) * CN + n) * CDH + dh);
#pragma unroll
            for (int i = 0; i < NU4; i++) pa[i] = *(const uint4*)(p + i * 8);
        } else {
            const bf16* p = Ab + (size_t)(rowBase + arow) * lda + k0 + akg;
#pragma unroll
            for (int i = 0; i < NU4; i++) pa[i] = *(const uint4*)(p + i * 8);
        }
    };
    auto ldB = [&](int k0) {
#pragma unroll
        for (int i = 0; i < BPASS; i++)
            pbb[i] = *(const uint4*)(Bb + (size_t)(k0 + brow + i * RPPB) * ldb +
                                     colBase + bcol);
    };
    auto stage = [&](int k0) {
#pragma unroll
        for (int i = 0; i < NU4; i++)
            *(uint4*)&As[arow * AP + akg + i * 8] = pa[i];
#pragma unroll
        for (int i = 0; i < BPASS; i++) {
            int r = brow + i * RPPB;
            uint4 u;
            if (DIAG) {
                float e[8];
                float2 f;
                f = unpk(pbb[i].x); e[0] = f.x; e[1] = f.y;
                f = unpk(pbb[i].y); e[2] = f.x; e[3] = f.y;
                f = unpk(pbb[i].z); e[4] = f.x; e[5] = f.y;
                f = unpk(pbb[i].w); e[6] = f.x; e[7] = f.y;
                int kr = k0 + r;
                int cb = colBase + bcol;
#pragma unroll
                for (int j = 0; j < 8; j++)
                    e[j] = bsign * e[j] + ((kr == cb + j) ? diagc : 0.0f);
                u.x = pack2(e[0], e[1]); u.y = pack2(e[2], e[3]);
                u.z = pack2(e[4], e[5]); u.w = pack2(e[6], e[7]);
            } else {
                u = pbb[i];
            }
            *(uint4*)&Bs[r * BPH + bcol] = u;
        }
    };

    float acc[MI][NFR][4] = {};

    ldA(0); ldB(0); stage(0);
    __syncthreads();
    for (int k0 = 0;; k0 += 32) {
        const int kn = k0 + 32;
        const bool more = kn < K;
        if (more) { ldA(kn); ldB(kn); }
#pragma unroll
        for (int ks = 0; ks < 2; ks++) {
            uint32_t af[MI][4];
#pragma unroll
            for (int mi = 0; mi < MI; mi++)
                ldsm4(af[mi], aoff + ((wm * WROWS + mi * 16) * AP + ks * 16) * 2);
            uint32_t bfr[NFR][2];
#pragma unroll
            for (int np = 0; np < NFR / 2; np++)
                ldsm4t(bfr[2 * np][0], bfr[2 * np][1],
                       bfr[2 * np + 1][0], bfr[2 * np + 1][1],
                       boff + (ks * 16 * BPH + np * 16) * 2);
#pragma unroll
            for (int ni = 0; ni < NFR; ni++)
#pragma unroll
                for (int mi = 0; mi < MI; mi++)
                    mma16(acc[mi][ni], af[mi], bfr[ni][0], bfr[ni][1]);
        }
        if (!more) break;
        __syncthreads();
        stage(kn);
        __syncthreads();
    }

    // ------------------------------ epilogue -------------------------------
    bf16*  Cb16 = (bf16*)Cp + blockIdx.z * sC;
    float* Cbf  = (float*)Cp + blockIdx.z * sC;

    if (MODE == 3) {
        float* smax = sred;
        float* ssum = sred + BM * WGN;
#pragma unroll
        for (int mi = 0; mi < MI; mi++)
#pragma unroll
            for (int h2 = 0; h2 < 2; h2++) {
                float m = -3.4e38f;
#pragma unroll
                for (int ni = 0; ni < NFR; ni++) {
                    m = fmaxf(m, acc[mi][ni][h2 * 2]);
                    m = fmaxf(m, acc[mi][ni][h2 * 2 + 1]);
                }
                m = fmaxf(m, __shfl_xor_sync(0xffffffffu, m, 1));
                m = fmaxf(m, __shfl_xor_sync(0xffffffffu, m, 2));
                int rl = wm * WROWS + mi * 16 + h2 * 8 + g;
                if (tg == 0) smax[rl * WGN + wn] = m;
            }
        __syncthreads();
#pragma unroll
        for (int mi = 0; mi < MI; mi++)
#pragma unroll
            for (int h2 = 0; h2 < 2; h2++) {
                int rl = wm * WROWS + mi * 16 + h2 * 8 + g;
                float tm = smax[rl * WGN];
#pragma unroll
                for (int w = 1; w < WGN; w++) tm = fmaxf(tm, smax[rl * WGN + w]);
                float s = 0.0f;
#pragma unroll
                for (int ni = 0; ni < NFR; ni++) {
                    float e0 = expf(acc[mi][ni][h2 * 2]     - tm);
                    float e1 = expf(acc[mi][ni][h2 * 2 + 1] - tm);
                    acc[mi][ni][h2 * 2]     = e0;
                    acc[mi][ni][h2 * 2 + 1] = e1;
                    s += e0 + e1;
                }
                s += __shfl_xor_sync(0xffffffffu, s, 1);
                s += __shfl_xor_sync(0xffffffffu, s, 2);
                if (tg == 0) ssum[rl * WGN + wn] = s;
            }
        __syncthreads();
#pragma unroll
        for (int mi = 0; mi < MI; mi++)
#pragma unroll
            for (int h2 = 0; h2 < 2; h2++) {
                int rl = wm * WROWS + mi * 16 + h2 * 8 + g;
                float s = 0.0f;
#pragma unroll
                for (int w = 0; w < WGN; w++) s += ssum[rl * WGN + w];
                float inv = 1.0f / s;
                int r = rowBase + rl;
#pragma unroll
                for (int ni = 0; ni < NFR; ni++) {
                    int c0 = colBase + wn * WCOLS + ni * 8 + 2 * tg;
                    *(uint32_t*)&Cb16[(size_t)r * ldc + c0] =
                        pack2(acc[mi][ni][h2 * 2] * inv,
                              acc[mi][ni][h2 * 2 + 1] * inv);
                }
            }
        return;
    }

#pragma unroll
    for (int mi = 0; mi < MI; mi++)
#pragma unroll
        for (int ni = 0; ni < NFR; ni++) {
            int r0 = rowBase + wm * WROWS + mi * 16 + g;
            int c0 = colBase + wn * WCOLS + ni * 8 + 2 * tg;
#pragma unroll
            for (int h2 = 0; h2 < 2; h2++) {
                int r = r0 + h2 * 8;
                float vx = alpha * acc[mi][ni][h2 * 2];
                float vy = alpha * acc[mi][ni][h2 * 2 + 1];
                if (MODE == 0) {
                    *(uint32_t*)&Cb16[(size_t)r * ldc + c0] = pack2(vx, vy);
                } else if (MODE == 4) {
                    uint32_t old = *(uint32_t*)&Cb16[(size_t)r * ldc + c0];
                    float2 f = unpk(old);
                    *(uint32_t*)&Cb16[(size_t)r * ldc + c0] =
                        pack2(vx + f.x, vy + f.y);
                } else if (MODE == 1) {
                    int b_ = r >> 12, n = r & (CN - 1);
                    int which = c0 >> 9, inner = c0 & 511;
                    int h_ = inner >> 6, dh = inner & 63;
                    size_t off = (((size_t)(b_ * CH + h_)) * CN + n) * CDH + dh;
                    if (which == 0) {
                        *(uint32_t*)&g_q[off] = pack2(vx * 0.125f, vy * 0.125f);
                    } else if (which == 1) {
                        size_t ot = (((size_t)(b_ * CH + h_)) * CDH + dh) * CN + n;
                        g_kT[ot]      = __float2bfloat16(vx);
                        g_kT[ot + CN] = __float2bfloat16(vy);
                    } else {
                        *(uint32_t*)&g_v[off] = pack2(vx, vy);
                    }
                } else {
                    size_t o = (size_t)r * CD + c0;
                    float2 xr = *(const float2*)&X[o];
                    float2 br = *(const float2*)&bias[c0];
                    *(float2*)&Cbf[o] = make_float2(vx + xr.x + br.x,
                                                    vy + xr.y + br.y);
                }
            }
        }
}

// ---------------------------------------------------------------------------
// Weight conversion fp32 -> bf16 (Wqkv, Wout)
// ---------------------------------------------------------------------------
__global__ void convert_w(const float* __restrict__ Wqkv,
                          const float* __restrict__ Wout) {
    int i = (blockIdx.x * 256 + threadIdx.x) * 4;
    const int n1 = CD * CT3;
    if (i < n1) {
        float4 v = *(const float4*)&Wqkv[i];
        uint2 o; o.x = pack2(v.x, v.y); o.y = pack2(v.z, v.w);
        *(uint2*)&g_wq16[i] = o;
    }
    if (i < CD * CD) {
        float4 v = *(const float4*)&Wout[i];
        uint2 o; o.x = pack2(v.x, v.y); o.y = pack2(v.z, v.w);
        *(uint2*)&g_wo16[i] = o;
    }
}

// ---------------------------------------------------------------------------
// LayerNorm -> bf16
// ---------------------------------------------------------------------------
__global__ void ln_kernel(const float* __restrict__ x,
                          const float* __restrict__ gamma,
                          const float* __restrict__ beta) {
    int row = blockIdx.x;
    int t = threadIdx.x;  // 128
    const float4* xr = (const float4*)(x + (size_t)row * CD);
    float4 v = xr[t];
    float s  = v.x + v.y + v.z + v.w;
    float ss = v.x * v.x + v.y * v.y + v.z * v.z + v.w * v.w;
    __shared__ float shs[4], shss[4];
#pragma unroll
    for (int o = 16; o > 0; o >>= 1) {
        s  += __shfl_down_sync(0xffffffffu, s,  o);
        ss += __shfl_down_sync(0xffffffffu, ss, o);
    }
    int wid = t >> 5, lane = t & 31;
    if (!lane) { shs[wid] = s; shss[wid] = ss; }
    __syncthreads();
    s  = shs[0]  + shs[1]  + shs[2]  + shs[3];
    ss = shss[0] + shss[1] + shss[2] + shss[3];
    float mean = s * (1.0f / CD);
    float var  = ss * (1.0f / CD) - mean * mean;
    float inv  = rsqrtf(var + EPS);
    float4 gg = ((const float4*)gamma)[t];
    float4 bb = ((const float4*)beta)[t];
    uint2 o;
    o.x = pack2((v.x - mean) * inv * gg.x + bb.x, (v.y - mean) * inv * gg.y + bb.y);
    o.y = pack2((v.z - mean) * inv * gg.z + bb.z, (v.w - mean) * inv * gg.w + bb.w);
    *(uint2*)&g_xn[(size_t)row * CD + t * 4] = o;
}

// ---------------------------------------------------------------------------
// Landmark means (q from g_q, k from g_kT)
// ---------------------------------------------------------------------------
__global__ void landmark_kernel() {
    int idx = blockIdx.x * 256 + threadIdx.x;  // BH*M*DH
    int dh = idx & 63;
    int mi = (idx >> 6) & 255;
    int bh = idx >> 14;
    size_t qbase = ((size_t)bh * CN + mi * CL) * CDH + dh;
    float sq = 0.0f;
#pragma unroll
    for (int j = 0; j < CL; j++)
        sq += __bfloat162float(g_q[qbase + (size_t)j * CDH]);
    size_t kbase = ((size_t)bh * CDH + dh) * CN + mi * CL;
    float sk = 0.0f;
#pragma unroll
    for (int j = 0; j < CL; j++)
        sk += __bfloat162float(g_kT[kbase + j]);
    g_ql [((size_t)bh * CM + mi) * CDH + dh] = __float2bfloat16(sq * (1.0f / CL));
    g_klT[((size_t)bh * CDH + dh) * CM + mi] = __float2bfloat16(sk * (1.0f / CL));
}

// ---------------------------------------------------------------------------
// Row softmax for a3 (rows of 4096)
// ---------------------------------------------------------------------------
template <int IT>
__global__ void softmax_rows(bf16* __restrict__ p, int len) {
    bf16* r = p + (size_t)blockIdx.x * len;
    int t = threadIdx.x;
    float vals[IT];
    float mx = -3.4e38f;
#pragma unroll
    for (int i = 0; i < IT; i++) {
        vals[i] = __bfloat162float(r[t + i * 256]);
        mx = fmaxf(mx, vals[i]);
    }
    __shared__ float sh[8];
#pragma unroll
    for (int o = 16; o > 0; o >>= 1) mx = fmaxf(mx, __shfl_xor_sync(0xffffffffu, mx, o));
    int wid = t >> 5, lane = t & 31;
    if (!lane) sh[wid] = mx;
    __syncthreads();
    mx = sh[0];
#pragma unroll
    for (int w = 1; w < 8; w++) mx = fmaxf(mx, sh[w]);
    __syncthreads();
    float s = 0.0f;
#pragma unroll
    for (int i = 0; i < IT; i++) {
        vals[i] = expf(vals[i] - mx);
        s += vals[i];
    }
#pragma unroll
    for (int o = 16; o > 0; o >>= 1) s += __shfl_xor_sync(0xffffffffu, s, o);
    if (!lane) sh[wid] = s;
    __syncthreads();
    s = sh[0];
#pragma unroll
    for (int w = 1; w < 8; w++) s += sh[w];
    float inv = 1.0f / s;
#pragma unroll
    for (int i = 0; i < IT; i++) r[t + i * 256] = __float2bfloat16(vals[i] * inv);
}

// ---------------------------------------------------------------------------
// Pinv init
// ---------------------------------------------------------------------------
__global__ void init_scalars() { g_maxc = 0u; g_maxr = 0u; }

__global__ void absmax_sums() {
    int bh = blockIdx.x;
    int t = threadIdx.x;
    const bf16* a = g_a2 + (size_t)bh * CM * CM;
    float rs = 0.0f, cs = 0.0f;
    for (int j = 0; j < CM; j++) rs += fabsf(__bfloat162float(a[(size_t)t * CM + j]));
    for (int i = 0; i < CM; i++) cs += fabsf(__bfloat162float(a[(size_t)i * CM + t]));
    atomicMax(&g_maxc, __float_as_uint(rs));
    atomicMax(&g_maxr, __float_as_uint(cs));
}

__global__ void zinit_kernel() {
    int idx = blockIdx.x * 256 + threadIdx.x;
    int j = idx & 255;
    int i = (idx >> 8) & 255;
    int bh = idx >> 16;
    float denom = __uint_as_float(g_maxc) * __uint_as_float(g_maxr);
    g_z[((size_t)bh << 16) + (size_t)i * CM + j] =
        __float2bfloat16(__bfloat162float(g_a2[((size_t)bh << 16) + (size_t)j * CM + i]) / denom);
}

// ---------------------------------------------------------------------------
// Depthwise conv residual (sliding window, 4 outputs/thread) — WRITES g_outh
// ---------------------------------------------------------------------------
__global__ void conv_res(const float* __restrict__ w) {
    __shared__ float ws[33];
    int idx = blockIdx.x * 256 + threadIdx.x;
    int dh = idx & 63;
    int nq = (idx >> 6) & 1023;   // CN/4
    int bh = idx >> 16;
    int h_ = bh & 7;
    if (threadIdx.x < 33) ws[threadIdx.x] = w[h_ * 33 + threadIdx.x];
    __syncthreads();
    int n0 = nq * 4;
    size_t base = ((size_t)bh * CN) * CDH + dh;
    float vv[36];
#pragma unroll
    for (int j = 0; j < 36; j++) {
        int nn = n0 - 16 + j;
        vv[j] = (nn >= 0 && nn < CN)
                    ? __bfloat162float(g_v[base + (size_t)nn * CDH]) : 0.0f;
    }
#pragma unroll
    for (int i = 0; i < 4; i++) {
        float s = 0.0f;
#pragma unroll
        for (int k2 = 0; k2 < 33; k2++) s += ws[k2] * vv[k2 + i];
        g_outh[base + (size_t)(n0 + i) * CDH] = __float2bfloat16(s);
    }
}

// ---------------------------------------------------------------------------
// Launch (fork/join: pinv chain on s1 overlaps attention branch on s0)
// ---------------------------------------------------------------------------
extern "C" void kernel_launch(void* const* d_in, const int* in_sizes, int n_in,
                              void* d_out, int out_size) {
    const float* x     = (const float*)d_in[0];
    const float* gamma = (const float*)d_in[1];
    const float* beta  = (const float*)d_in[2];
    const float* Wqkv  = (const float*)d_in[3];
    const float* Wout  = (const float*)d_in[4];
    const float* bout  = (const float*)d_in[5];
    const float* convw = (const float*)d_in[6];
    float* out = (float*)d_out;

    bf16 *xn, *q, *v, *kT, *ql, *klT, *a1, *a3, *a2;
    bf16 *z, *z2, *xz, *tb, *ub, *av, *zav, *outh, *wq16, *wo16;
    void* p;
    cudaGetSymbolAddress(&p, g_xn);   xn   = (bf16*)p;
    cudaGetSymbolAddress(&p, g_q);    q    = (bf16*)p;
    cudaGetSymbolAddress(&p, g_v);    v    = (bf16*)p;
    cudaGetSymbolAddress(&p, g_kT);   kT   = (bf16*)p;
    cudaGetSymbolAddress(&p, g_ql);   ql   = (bf16*)p;
    cudaGetSymbolAddress(&p, g_klT);  klT  = (bf16*)p;
    cudaGetSymbolAddress(&p, g_a1);   a1   = (bf16*)p;
    cudaGetSymbolAddress(&p, g_a3);   a3   = (bf16*)p;
    cudaGetSymbolAddress(&p, g_a2);   a2   = (bf16*)p;
    cudaGetSymbolAddress(&p, g_z);    z    = (bf16*)p;
    cudaGetSymbolAddress(&p, g_z2);   z2   = (bf16*)p;
    cudaGetSymbolAddress(&p, g_xz);   xz   = (bf16*)p;
    cudaGetSymbolAddress(&p, g_t);    tb   = (bf16*)p;
    cudaGetSymbolAddress(&p, g_u);    ub   = (bf16*)p;
    cudaGetSymbolAddress(&p, g_av);   av   = (bf16*)p;
    cudaGetSymbolAddress(&p, g_zav);  zav  = (bf16*)p;
    cudaGetSymbolAddress(&p, g_outh); outh = (bf16*)p;
    cudaGetSymbolAddress(&p, g_wq16); wq16 = (bf16*)p;
    cudaGetSymbolAddress(&p, g_wo16); wo16 = (bf16*)p;

    const size_t MM  = (size_t)CM * CM;
    const size_t NDH = (size_t)CN * CDH;
    cudaStream_t s1 = g_aux.s1;

    // --- common prefix on default stream ---
    ln_kernel<<<CB * CN, 128>>>(x, gamma, beta);
    convert_w<<<(CD * CT3) / 1024, 256>>>(Wqkv, Wout);
    tc_gemm<128, 256, 2, 4, 1, false, 1><<<dim3(CT3 / 256, CB * CN / 128, 1), 256>>>(
        xn, wq16, nullptr, CD, CD, CT3, 0, 0, 0, 0, 1.0f, 0.0f, 1.0f, nullptr, nullptr);
    landmark_kernel<<<(CBH * CM * CDH) / 256, 256>>>();
    cudaEventRecord(g_aux.evF, 0);

    // --- stream s1: a2 + pinv chain ---
    cudaStreamWaitEvent(s1, g_aux.evF, 0);
    tc_gemm<128, 256, 2, 4, 3, false, 1><<<dim3(1, CM / 128, CBH), 256, 0, s1>>>(
        ql, klT, a2, CDH, CDH, CM, CM,
        (size_t)CM * CDH, (size_t)CDH * CM, MM, 1.0f, 0.0f, 1.0f, nullptr, nullptr);
    init_scalars<<<1, 1, 0, s1>>>();
    absmax_sums<<<CBH, 256, 0, s1>>>();
    zinit_kernel<<<(CBH * CM * CM) / 256, 256, 0, s1>>>();
    bf16* zc = z;
    bf16* zn = z2;
    for (int it = 0; it < 6; it++) {
        tc_gemm<128, 128, 2, 4, 0, false, 2><<<dim3(2, 2, CBH), 256, 0, s1>>>(
            a2, zc, xz, CM, CM, CM, CM, MM, MM, MM, 1.0f, 0.0f, 1.0f, nullptr, nullptr);
        tc_gemm<128, 128, 2, 4, 0, true, 2><<<dim3(2, 2, CBH), 256, 0, s1>>>(
            xz, xz, tb, CM, CM, CM, CM, MM, MM, MM, 1.0f, 7.0f, -1.0f, nullptr, nullptr);
        tc_gemm<128, 128, 2, 4, 0, true, 2><<<dim3(2, 2, CBH), 256, 0, s1>>>(
            xz, tb, ub, CM, CM, CM, CM, MM, MM, MM, 1.0f, 15.0f, -1.0f, nullptr, nullptr);
        tc_gemm<128, 128, 2, 4, 0, true, 2><<<dim3(2, 2, CBH), 256, 0, s1>>>(
            zc, ub, zn, CM, CM, CM, CM, MM, MM, MM, 0.25f, 13.0f, -1.0f, nullptr, nullptr);
        bf16* tmp = zc; zc = zn; zn = tmp;
    }
    cudaEventRecord(g_aux.evJ, s1);

    // --- default stream: attention branch (overlaps pinv) ---
    tc_gemm<128, 256, 2, 4, 3, false, 1><<<dim3(1, CN / 128, CBH), 256>>>(
        q, klT, a1, CDH, CDH, CM, CM,
        NDH, (size_t)CDH * CM, (size_t)CN * CM, 1.0f, 0.0f, 1.0f, nullptr, nullptr);
    tc_gemm<128, 256, 2, 4, 0, false, 1><<<dim3(CN / 256, CM / 128, CBH), 256>>>(
        ql, kT, a3, CDH, CDH, CN, CN,
        (size_t)CM * CDH, (size_t)CDH * CN, (size_t)CM * CN, 1.0f, 0.0f, 1.0f,
        nullptr, nullptr);
    softmax_rows<16><<<CBH * CM, 256>>>(a3, CN);
    tc_gemm<64, 64, 4, 2, 0, false, 2><<<dim3(1, CM / 64, CBH), 256>>>(
        a3, v, av, CN, CN, CDH, CDH,
        (size_t)CM * CN, NDH, (size_t)CM * CDH, 1.0f, 0.0f, 1.0f, nullptr, nullptr);
    conv_res<<<(CBH * CN * CDH) / 1024, 256>>>(convw);

    // --- join, then tail on default stream ---
    cudaStreamWaitEvent(0, g_aux.evJ, 0);
    tc_gemm<64, 64, 4, 2, 0, false, 2><<<dim3(1, CM / 64, CBH), 256>>>(
        zc, av, zav, CM, CM, CDH, CDH,
        MM, (size_t)CM * CDH, (size_t)CM * CDH, 1.0f, 0.0f, 1.0f, nullptr, nullptr);
    tc_gemm<128, 64, 4, 2, 4, false, 2><<<dim3(1, CN / 128, CBH), 256>>>(
        a1, zav, outh, CM, CM, CDH, CDH,
        (size_t)CN * CM, (size_t)CM * CDH, NDH, 1.0f, 0.0f, 1.0f, nullptr, nullptr);
    tc_gemm<128, 256, 2, 4, 2, false, 1><<<dim3(CD / 256, CB * CN / 128, 1), 256>>>(
        outh, wo16, out, CD, 0, CD, CD, 0, 0, 0, 1.0f, 0.0f, 1.0f, x, bout);
}